// round 11
// baseline (speedup 1.0000x reference)
#include <cuda_runtime.h>
#include <cuda_fp16.h>
#include <cstdint>

#define BSZ_   2
#define DM_    1024
#define QL_    2048
#define NH_    16
#define DH_    64
#define LOCAL_ 1000
#define SCALE_ 0.125f
#define RPAD_  2176
#define CML_   (0.125f * 1.44269504088896f)   // scale * log2(e)

// ---------------- scratch (__device__ globals; zero-initialized) ---------------
__device__ __align__(16) __half h_Wqkv[3*DM_*DM_];
__device__ __align__(16) __half h_Wr[DM_*DM_];
__device__ __align__(16) __half h_Wo[DM_*DM_];
__device__ __align__(16) __half h_Z[BSZ_*DM_*QL_];
__device__ __align__(16) __half h_Pe[DM_*QL_];
__device__ __align__(16) __half g_Qh[BSZ_*DM_*QL_];
__device__ __align__(16) __half g_Kh[BSZ_*DM_*QL_];
__device__ __align__(16) __half g_Vh[BSZ_*DM_*QL_];
__device__ __align__(16) __half g_Rh[DM_*RPAD_];
__device__ __align__(16) __half g_AVh[BSZ_*DM_*QL_];
__device__ __align__(16) float  g_TMP[BSZ_*DM_*QL_];

__device__ __forceinline__ uint32_t f22u(float a, float b) {
    __half2 h = __floats2half2_rn(a, b);
    return *reinterpret_cast<uint32_t*>(&h);
}
__device__ __forceinline__ uint32_t h2ex2(float a, float b) {
    uint32_t h = f22u(a, b), r;
    asm("ex2.approx.f16x2 %0, %1;" : "=r"(r) : "r"(h));
    return r;
}

#define MMA_F16(C, A, B)                                                        \
    asm volatile(                                                               \
        "mma.sync.aligned.m16n8k16.row.col.f32.f16.f16.f32 "                    \
        "{%0,%1,%2,%3}, {%4,%5,%6,%7}, {%8,%9}, {%0,%1,%2,%3};"                 \
        : "+f"((C)[0]), "+f"((C)[1]), "+f"((C)[2]), "+f"((C)[3])                \
        : "r"((A)[0]), "r"((A)[1]), "r"((A)[2]), "r"((A)[3]),                   \
          "r"((B)[0]), "r"((B)[1]))

#define LDSM4(R, addr)                                                          \
    asm volatile("ldmatrix.sync.aligned.m8n8.x4.shared.b16 {%0,%1,%2,%3}, [%4];"\
        : "=r"((R)[0]), "=r"((R)[1]), "=r"((R)[2]), "=r"((R)[3]) : "r"(addr))

#define LDSM4T(R, addr)                                                         \
    asm volatile("ldmatrix.sync.aligned.m8n8.x4.trans.shared.b16 {%0,%1,%2,%3}, [%4];"\
        : "=r"((R)[0]), "=r"((R)[1]), "=r"((R)[2]), "=r"((R)[3]) : "r"(addr))

#define CPA16(dst, src)                                                         \
    asm volatile("cp.async.cg.shared.global [%0], [%1], 16;" :: "r"(dst), "l"(src))
#define CP_COMMIT asm volatile("cp.async.commit_group;")
#define CP_WAIT0  asm volatile("cp.async.wait_group 0;" ::: "memory")
#define CP_WAIT1  asm volatile("cp.async.wait_group 1;" ::: "memory")

// ---------------- fused fp32 -> fp16 conversion (one launch) -------------------
#define F2H_N4 2883584
__global__ void f2h_all(const float* __restrict__ z, const float* __restrict__ pos,
                        const float* __restrict__ wqkv, const float* __restrict__ wr,
                        const float* __restrict__ wo)
{
    const int nW = 3*DM_*DM_/4, nR = DM_*DM_/4, nZ = BSZ_*DM_*QL_/4, nP = DM_*QL_/4;
    int off = blockIdx.x * blockDim.x + threadIdx.x;
    const float* src; __half* dst;
    if (off < nW)              { src = wqkv; dst = h_Wqkv; }
    else if ((off -= nW) < nR) { src = wr;   dst = h_Wr;  }
    else if ((off -= nR) < nR) { src = wo;   dst = h_Wo;  }
    else if ((off -= nR) < nZ) { src = z;    dst = h_Z;   }
    else if ((off -= nZ) < nP) { src = pos;  dst = h_Pe;  }
    else return;
    float4 v = ((const float4*)src)[off];
    uint2 o = { f22u(v.x, v.y), f22u(v.z, v.w) };
    ((uint2*)dst)[off] = o;
}

// =====================================================================
// fp16 GEMM, 3-stage cp.async (R7 proven config). k-tile 32.
// mode 3: fused QKV (+u1ss) + Wr;  mode 2: Wo
// =====================================================================
#define GA_BUF 10240
#define GB_BUF 8704
#define GSTG   (GA_BUF + GB_BUF)
#define GEMM_SMEM (3 * GSTG)

__global__ void __launch_bounds__(256, 2) gemm_tc(
    const float* __restrict__ U, const float* __restrict__ bias, int K, int mode)
{
    extern __shared__ char smc[];
    const uint32_t sbase = (uint32_t)__cvta_generic_to_shared(smc);

    int emode, bb, my;
    if (mode == 3) {
        int y = blockIdx.y;
        if (y < 48) { emode = 0; bb = y / 24; my = y % 24; }
        else        { emode = 1; bb = 0;      my = y - 48; }
    } else { emode = 2; bb = blockIdx.z; my = blockIdx.y; }

    const int N = QL_;
    const __half* A = (emode == 0) ? h_Wqkv : (emode == 1) ? h_Wr : h_Wo;
    const __half* B = (emode == 0) ? h_Z + (size_t)bb * K * N
                    : (emode == 1) ? h_Pe
                    : g_AVh + (size_t)bb * DM_ * QL_;

    const int m0 = my * 128, n0 = blockIdx.x * 128;
    const int tid = threadIdx.x, lane = tid & 31, wid = tid >> 5;
    const int g = lane >> 2, q = lane & 3;
    const int wm = wid >> 2, wn = wid & 3;

    const int a_row = tid >> 1, a_c = (tid & 1) * 2;
    const int b_row = tid >> 3, b_c = (tid & 7) * 2;
    const __half* AgB = A + (size_t)(m0 + a_row) * K + a_c * 8;
    const __half* BgB = B + (size_t)b_row * N + n0 + b_c * 8;
    const uint32_t daB = sbase + (a_row * 40 + a_c * 8) * 2;
    const uint32_t dbB = sbase + GA_BUF + (b_row * 136 + b_c * 8) * 2;

    uint32_t a_addr[4], b_addr[2];
    #pragma unroll
    for (int tm = 0; tm < 4; tm++)
        a_addr[tm] = sbase + ((wm * 64 + tm * 16 + (lane & 15)) * 40 + (lane >> 4) * 8) * 2;
    #pragma unroll
    for (int p = 0; p < 2; p++)
        b_addr[p] = sbase + GA_BUF + ((lane & 15) * 136 + wn * 32 + p * 16 + (lane >> 4) * 8) * 2;

    float acc[4][4][4];
    #pragma unroll
    for (int i = 0; i < 4; i++)
        #pragma unroll
        for (int j = 0; j < 4; j++)
            #pragma unroll
            for (int c = 0; c < 4; c++) acc[i][j][c] = 0.0f;

    const int nt = K / 32;
    #pragma unroll
    for (int t = 0; t < 2; t++) {
        const uint32_t so = t * GSTG;
        const __half* bs = BgB + (size_t)(t * 32) * N;
        CPA16(daB + so, AgB + t * 32); CPA16(daB + so + 16, AgB + t * 32 + 8);
        CPA16(dbB + so, bs);           CPA16(dbB + so + 16, bs + 8);
        CP_COMMIT;
    }

    int buf0 = 0, buf2 = 2;
    for (int t = 0; t < nt; t++) {
        CP_WAIT1;
        __syncthreads();
        if (t + 2 < nt) {
            const int k1 = (t + 2) * 32;
            const uint32_t so = buf2 * GSTG;
            const __half* bs = BgB + (size_t)k1 * N;
            CPA16(daB + so, AgB + k1); CPA16(daB + so + 16, AgB + k1 + 8);
            CPA16(dbB + so, bs);       CPA16(dbB + so + 16, bs + 8);
        }
        CP_COMMIT;
        const uint32_t so = buf0 * GSTG;
        #pragma unroll
        for (int kk = 0; kk < 2; kk++) {
            uint32_t af[4][4], bt[2][4];
            #pragma unroll
            for (int tm = 0; tm < 4; tm++) LDSM4(af[tm], a_addr[tm] + so + kk * 32);
            #pragma unroll
            for (int p = 0; p < 2; p++)    LDSM4T(bt[p], b_addr[p] + so + kk * 16 * 136 * 2);
            #pragma unroll
            for (int tm = 0; tm < 4; tm++)
                #pragma unroll
                for (int tn = 0; tn < 4; tn++)
                    MMA_F16(acc[tm][tn], af[tm], &bt[tn >> 1][(tn & 1) * 2]);
        }
        buf0 = (buf0 == 2) ? 0 : buf0 + 1;
        buf2 = (buf2 == 2) ? 0 : buf2 + 1;
    }

    #pragma unroll
    for (int tm = 0; tm < 4; tm++) {
        #pragma unroll
        for (int half = 0; half < 2; half++) {
            const int m = m0 + wm * 64 + tm * 16 + g + half * 8;
            #pragma unroll
            for (int tn = 0; tn < 4; tn++) {
                const int n = n0 + wn * 32 + tn * 8 + 2 * q;
                float v0 = acc[tm][tn][half * 2 + 0];
                float v1 = acc[tm][tn][half * 2 + 1];
                if (emode == 0) {
                    const float2 u = *(const float2*)&U[((size_t)bb * 3 * DM_ + m) * QL_ + n];
                    v0 += u.x; v1 += u.y;
                    const int which = m >> 10, rem = m & 1023;
                    __half* dst = (which == 0) ? g_Qh : (which == 1) ? g_Kh : g_Vh;
                    *(uint32_t*)&dst[((size_t)bb * DM_ + rem) * QL_ + n] = f22u(v0, v1);
                } else if (emode == 1) {
                    *(uint32_t*)&g_Rh[(size_t)m * RPAD_ + n] = f22u(v0, v1);
                } else {
                    const float bbia = bias[m];
                    const float2 u = *(const float2*)&U[((size_t)bb * DM_ + m) * QL_ + n];
                    v0 += bbia + u.x; v1 += bbia + u.y;
                    *(float2*)&g_TMP[((size_t)bb * DM_ + m) * QL_ + n] = make_float2(v0, v1);
                }
            }
        }
    }
}

// =====================================================================
// FA2-style fp16 attention: 128 threads, warp = 16 rows x 64 cols
// S / P / O / m / l all register-resident; E via per-warp smem gather.
// smem 105 KB, 2 CTA/SM, ONE CTA barrier per tile.
// =====================================================================
#define H_QW 0
#define H_QR 9216
#define H_K  18432        // 2 x 9216  (64 x 72 halves each)
#define H_V  36864        // 2 x 9216
#define H_R  55296        // 2 x 17408 (64 x 136 halves each)
#define H_E  90112        // 64 x 136 halves (fp32 64x68 scratch in epilogue)
#define ATTN_SMEM 107520

__global__ void __launch_bounds__(128, 2) attn_tc(
    const float* __restrict__ rwb_all, const float* __restrict__ rrb_all)
{
    extern __shared__ char smc[];
    const uint32_t sb = (uint32_t)__cvta_generic_to_shared(smc);
    __half* hQW = (__half*)(smc + H_QW);
    __half* hQR = (__half*)(smc + H_QR);
    __half* hE  = (__half*)(smc + H_E);

    const int b = blockIdx.z, n = blockIdx.y;
    const int i0 = blockIdx.x * 64;
    const int tid = threadIdx.x;
    const int lane = tid & 31, wid = tid >> 5;   // wid 0..3
    const int g = lane >> 2, q = lane & 3;

    const __half* Qh = g_Qh + ((size_t)b * DM_ + n * DH_) * QL_;
    const __half* Kh = g_Kh + ((size_t)b * DM_ + n * DH_) * QL_;
    const __half* Vh = g_Vh + ((size_t)b * DM_ + n * DH_) * QL_;
    const __half* Rh = g_Rh + (size_t)(n * DH_) * RPAD_;

    // ---- Q staging: [d][i] -> [i][d] with biases ----
    for (int idx = tid; idx < 64 * 16; idx += 128) {
        int d = idx >> 4, ic = (idx & 15) * 4;
        uint2 u = *(const uint2*)&Qh[(size_t)d * QL_ + i0 + ic];
        float2 v01 = __half22float2(*(__half2*)&u.x);
        float2 v23 = __half22float2(*(__half2*)&u.y);
        float w = rwb_all[n * DH_ + d];
        float r = rrb_all[n * DH_ + d];
        float vv[4] = {v01.x, v01.y, v23.x, v23.y};
        #pragma unroll
        for (int c = 0; c < 4; c++) {
            hQW[(ic + c) * 72 + d] = __float2half_rn(vv[c] + w);
            hQR[(ic + c) * 72 + d] = __float2half_rn(vv[c] + r);
        }
    }

    // ---- cp.async mappings (128 threads) ----
    const int cp_row = tid >> 1;                 // d row 0..63
    const int kv_off = (tid & 1) * 32;           // halves within row
    const int r_off  = (tid & 1) * 64;
    const uint32_t dK = sb + H_K + (cp_row * 72 + kv_off) * 2;
    const uint32_t dV = sb + H_V + (cp_row * 72 + kv_off) * 2;
    const uint32_t dR = sb + H_R + (cp_row * 136 + r_off) * 2;
    const __half* sKg = Kh + (size_t)cp_row * QL_ + kv_off;
    const __half* sVg = Vh + (size_t)cp_row * QL_ + kv_off;
    const __half* sRg = Rh + (size_t)cp_row * RPAD_ + r_off;

    // ---- ldmatrix base addresses ----
    const uint32_t qw_addr = sb + H_QW + ((wid * 16 + (lane & 15)) * 72 + (lane >> 4) * 8) * 2;
    const uint32_t qr_addr = sb + H_QR + ((wid * 16 + (lane & 15)) * 72 + (lane >> 4) * 8) * 2;
    const uint32_t k_addr  = sb + H_K + ((lane & 15) * 72 + (lane >> 4) * 8) * 2;
    const uint32_t r_addr  = sb + H_R + ((lane & 15) * 136 + (lane >> 4) * 8) * 2;
    const uint32_t v_addr  = sb + H_V + (((lane & 7) + (lane >> 4) * 8) * 72 + ((lane >> 3) & 1) * 8) * 2;

    float accO[8][4];
    #pragma unroll
    for (int nb = 0; nb < 8; nb++)
        #pragma unroll
        for (int c = 0; c < 4; c++) accO[nb][c] = 0.0f;
    float m0r = -1e30f, m1r = -1e30f, l0r = 0.0f, l1r = 0.0f;

    const int r0l = wid * 16 + g, r1l = r0l + 8;
    const int gi0 = i0 + r0l, gi1 = i0 + r1l;

    int jlo = i0 - (LOCAL_ - 1); if (jlo < 0) jlo = 0; jlo &= ~63;
    const int ntile = (i0 - jlo) / 64 + 1;

    {   // prologue: K/V/R tile 0 -> buf 0
        const int rbase = jlo - i0 + (QL_ - 1) - 63;
        const __half* k0 = sKg + jlo; const __half* v0 = sVg + jlo;
        const __half* r0 = sRg + rbase;
        CPA16(dK, k0); CPA16(dK + 16, k0 + 8); CPA16(dK + 32, k0 + 16); CPA16(dK + 48, k0 + 24);
        CPA16(dV, v0); CPA16(dV + 16, v0 + 8); CPA16(dV + 32, v0 + 16); CPA16(dV + 48, v0 + 24);
        #pragma unroll
        for (int c = 0; c < 8; c++) CPA16(dR + c * 16, r0 + c * 8);
        CP_COMMIT;
    }

    for (int t = 0; t < ntile; t++) {
        const int j0 = jlo + t * 64;
        CP_WAIT0;
        __syncthreads();
        if (t + 1 < ntile) {
            const int j1 = j0 + 64;
            const int rb1 = j1 - i0 + (QL_ - 1) - 63;
            const uint32_t kb1 = ((t + 1) & 1) * 9216;
            const uint32_t rb1b = ((t + 1) & 1) * 17408;
            const __half* k1 = sKg + j1; const __half* v1 = sVg + j1;
            const __half* r1 = sRg + rb1;
            CPA16(dK + kb1, k1); CPA16(dK + kb1 + 16, k1 + 8);
            CPA16(dK + kb1 + 32, k1 + 16); CPA16(dK + kb1 + 48, k1 + 24);
            CPA16(dV + kb1, v1); CPA16(dV + kb1 + 16, v1 + 8);
            CPA16(dV + kb1 + 32, v1 + 16); CPA16(dV + kb1 + 48, v1 + 24);
            #pragma unroll
            for (int c = 0; c < 8; c++) CPA16(dR + rb1b + c * 16, r1 + c * 8);
            CP_COMMIT;
        }
        const uint32_t kb = (t & 1) * 9216;
        const uint32_t rb = (t & 1) * 17408;

        // ---- S = QW^T K : accS[8][4] in registers ----
        float accS[8][4];
        #pragma unroll
        for (int nb = 0; nb < 8; nb++)
            #pragma unroll
            for (int c = 0; c < 4; c++) accS[nb][c] = 0.0f;
        #pragma unroll
        for (int kk = 0; kk < 4; kk++) {
            uint32_t aw[4], bk[4][4];
            LDSM4(aw, qw_addr + kk * 32);
            #pragma unroll
            for (int p = 0; p < 4; p++) LDSM4T(bk[p], k_addr + kb + kk * 2304 + p * 32);
            #pragma unroll
            for (int nb = 0; nb < 8; nb++)
                MMA_F16(accS[nb], aw, &bk[nb >> 1][(nb & 1) * 2]);
        }

        // ---- E = QR^T R (two 64-col halves), spill to per-warp smem rows ----
        #pragma unroll
        for (int h = 0; h < 2; h++) {
            float accE[8][4];
            #pragma unroll
            for (int nb = 0; nb < 8; nb++)
                #pragma unroll
                for (int c = 0; c < 4; c++) accE[nb][c] = 0.0f;
            #pragma unroll
            for (int kk = 0; kk < 4; kk++) {
                uint32_t ar[4], br[4][4];
                LDSM4(ar, qr_addr + kk * 32);
                #pragma unroll
                for (int p = 0; p < 4; p++)
                    LDSM4T(br[p], r_addr + rb + kk * 4352 + (h * 4 + p) * 32);
                #pragma unroll
                for (int nb = 0; nb < 8; nb++)
                    MMA_F16(accE[nb], ar, &br[nb >> 1][(nb & 1) * 2]);
            }
            #pragma unroll
            for (int nb = 0; nb < 8; nb++) {
                int col = (h * 8 + nb) * 8 + 2 * q;
                *(uint32_t*)&hE[r0l * 136 + col] = f22u(accE[nb][0], accE[nb][1]);
                *(uint32_t*)&hE[r1l * 136 + col] = f22u(accE[nb][2], accE[nb][3]);
            }
        }
        __syncwarp();

        // ---- softmax on registers (quad reduction) ----
        {
            const bool needmask = (j0 == i0) || (j0 <= i0 + 63 - LOCAL_);
            float rmax0 = -1e30f, rmax1 = -1e30f;
            #pragma unroll
            for (int nb = 0; nb < 8; nb++) {
                int c0 = 8 * nb + 2 * q;
                float e00 = __half2float(hE[r0l * 136 + (c0 - r0l + 63)]);
                float e01 = __half2float(hE[r0l * 136 + (c0 - r0l + 64)]);
                float e10 = __half2float(hE[r1l * 136 + (c0 - r1l + 63)]);
                float e11 = __half2float(hE[r1l * 136 + (c0 - r1l + 64)]);
                float v00 = (accS[nb][0] + e00) * CML_;
                float v01 = (accS[nb][1] + e01) * CML_;
                float v10 = (accS[nb][2] + e10) * CML_;
                float v11 = (accS[nb][3] + e11) * CML_;
                if (needmask) {
                    int ja = j0 + c0, jb2 = ja + 1;
                    v00 = (ja  <= gi0 && ja  > gi0 - LOCAL_) ? v00 : -1e30f;
                    v01 = (jb2 <= gi0 && jb2 > gi0 - LOCAL_) ? v01 : -1e30f;
                    v10 = (ja  <= gi1 && ja  > gi1 - LOCAL_) ? v10 : -1e30f;
                    v11 = (jb2 <= gi1 && jb2 > gi1 - LOCAL_) ? v11 : -1e30f;
                }
                accS[nb][0] = v00; accS[nb][1] = v01;
                accS[nb][2] = v10; accS[nb][3] = v11;
                rmax0 = fmaxf(rmax0, fmaxf(v00, v01));
                rmax1 = fmaxf(rmax1, fmaxf(v10, v11));
            }
            rmax0 = fmaxf(rmax0, __shfl_xor_sync(0xffffffffu, rmax0, 1));
            rmax0 = fmaxf(rmax0, __shfl_xor_sync(0xffffffffu, rmax0, 2));
            rmax1 = fmaxf(rmax1, __shfl_xor_sync(0xffffffffu, rmax1, 1));
            rmax1 = fmaxf(rmax1, __shfl_xor_sync(0xffffffffu, rmax1, 2));
            float mn0 = fmaxf(m0r, rmax0), mn1 = fmaxf(m1r, rmax1);
            float cc0 = exp2f(m0r - mn0), cc1 = exp2f(m1r - mn1);

            uint32_t pw0[8], pw1[8];
            float rs0 = 0.0f, rs1 = 0.0f;
            #pragma unroll
            for (int nb = 0; nb < 8; nb++) {
                pw0[nb] = h2ex2(accS[nb][0] - mn0, accS[nb][1] - mn0);
                pw1[nb] = h2ex2(accS[nb][2] - mn1, accS[nb][3] - mn1);
                float2 f0 = __half22float2(*(__half2*)&pw0[nb]);
                float2 f1 = __half22float2(*(__half2*)&pw1[nb]);
                rs0 += f0.x + f0.y;
                rs1 += f1.x + f1.y;
            }
            rs0 += __shfl_xor_sync(0xffffffffu, rs0, 1);
            rs0 += __shfl_xor_sync(0xffffffffu, rs0, 2);
            rs1 += __shfl_xor_sync(0xffffffffu, rs1, 1);
            rs1 += __shfl_xor_sync(0xffffffffu, rs1, 2);
            l0r = l0r * cc0 + rs0;
            l1r = l1r * cc1 + rs1;
            m0r = mn0; m1r = mn1;

            #pragma unroll
            for (int nb = 0; nb < 8; nb++) {
                accO[nb][0] *= cc0; accO[nb][1] *= cc0;
                accO[nb][2] *= cc1; accO[nb][3] *= cc1;
            }

            // ---- PV: P fragments are register repacks of the softmax output ----
            #pragma unroll
            for (int kk = 0; kk < 4; kk++) {
                uint32_t ap[4] = { pw0[2 * kk], pw1[2 * kk], pw0[2 * kk + 1], pw1[2 * kk + 1] };
                #pragma unroll
                for (int p = 0; p < 4; p++) {
                    uint32_t bv[4];
                    LDSM4(bv, v_addr + kb + p * 2304 + kk * 32);
                    MMA_F16(accO[p * 2],     ap, &bv[0]);
                    MMA_F16(accO[p * 2 + 1], ap, &bv[2]);
                }
            }
        }
    }

    // ---- epilogue: /l, transpose via fp32 scratch in E region, half store ----
    __syncthreads();
    float* fX = (float*)(smc + H_E);   // 64 x 68 fp32
    const float il0 = 1.0f / l0r, il1 = 1.0f / l1r;
    #pragma unroll
    for (int nb = 0; nb < 8; nb++) {
        int c0 = 8 * nb + 2 * q;
        fX[(c0 + 0) * 68 + r0l] = accO[nb][0] * il0;
        fX[(c0 + 1) * 68 + r0l] = accO[nb][1] * il0;
        fX[(c0 + 0) * 68 + r1l] = accO[nb][2] * il1;
        fX[(c0 + 1) * 68 + r1l] = accO[nb][3] * il1;
    }
    __syncthreads();
    __half* AVh = g_AVh + ((size_t)b * DM_ + n * DH_) * QL_;
    for (int idx = tid; idx < 64 * 8; idx += 128) {
        int d = idx >> 3, ic = (idx & 7) * 8;
        const float* src = &fX[d * 68 + ic];
        uint4 o;
        o.x = f22u(src[0], src[1]); o.y = f22u(src[2], src[3]);
        o.z = f22u(src[4], src[5]); o.w = f22u(src[6], src[7]);
        *(uint4*)&AVh[(size_t)d * QL_ + i0 + ic] = o;
    }
}

// ---------------- post-LN over d_model per (b, q) ------------------------------
__global__ void __launch_bounds__(256) ln_kernel(float* __restrict__ out)
{
    const int b  = blockIdx.y;
    const int tx = threadIdx.x & 31;
    const int ty = threadIdx.x >> 5;
    const int q  = blockIdx.x * 32 + tx;
    const float* X = g_TMP + (size_t)b * DM_ * QL_;

    float s = 0.0f, s2 = 0.0f;
    for (int o = ty; o < DM_; o += 8) {
        float v = X[(size_t)o * QL_ + q];
        s += v; s2 += v * v;
    }
    __shared__ float sh[8][32], sh2[8][32];
    __shared__ float mu[32], rs[32];
    sh[ty][tx] = s; sh2[ty][tx] = s2;
    __syncthreads();
    if (ty == 0) {
        float ts = 0.0f, ts2 = 0.0f;
        #pragma unroll
        for (int k = 0; k < 8; k++) { ts += sh[k][tx]; ts2 += sh2[k][tx]; }
        float m = ts * (1.0f / DM_);
        float var = ts2 * (1.0f / DM_) - m * m;
        mu[tx] = m;
        rs[tx] = rsqrtf(var + 1e-5f);
    }
    __syncthreads();
    float m = mu[tx], r = rs[tx];
    float* O = out + (size_t)b * DM_ * QL_;
    for (int o = ty; o < DM_; o += 8)
        O[(size_t)o * QL_ + q] = (X[(size_t)o * QL_ + q] - m) * r;
}

// ---------------- launch --------------------------------------------------------
extern "C" void kernel_launch(void* const* d_in, const int* in_sizes, int n_in,
                              void* d_out, int out_size)
{
    const float* z1ss = (const float*)d_in[0];
    const float* pos  = (const float*)d_in[1];
    const float* u1ss = (const float*)d_in[2];
    const float* Wqkv = (const float*)d_in[3];
    const float* Wr   = (const float*)d_in[4];
    const float* rwb  = (const float*)d_in[5];
    const float* rrb  = (const float*)d_in[6];
    const float* Wo   = (const float*)d_in[7];
    const float* bo   = (const float*)d_in[8];
    float* out = (float*)d_out;

    cudaFuncSetAttribute(gemm_tc, cudaFuncAttributeMaxDynamicSharedMemorySize, GEMM_SMEM);
    cudaFuncSetAttribute(attn_tc, cudaFuncAttributeMaxDynamicSharedMemorySize, ATTN_SMEM);

    f2h_all<<<(F2H_N4 + 255) / 256, 256>>>(z1ss, pos, Wqkv, Wr, Wo);

    dim3 g0(QL_ / 128, 56, 1);   // fused QKV (48 y-blocks) + Wr (8 y-blocks)
    gemm_tc<<<g0, 256, GEMM_SMEM>>>(u1ss, nullptr, DM_, 3);

    dim3 ga(QL_ / 64, NH_, BSZ_);
    attn_tc<<<ga, 128, ATTN_SMEM>>>(rwb, rrb);

    dim3 g2(QL_ / 128, DM_ / 128, BSZ_);
    gemm_tc<<<g2, 256, GEMM_SMEM>>>(z1ss, bo, DM_, 2);

    dim3 g3(QL_ / 32, BSZ_);
    ln_kernel<<<g3, 256>>>(out);
}

// round 12
// speedup vs baseline: 1.4672x; 1.4672x over previous
#include <cuda_runtime.h>
#include <cuda_fp16.h>
#include <cstdint>

#define BSZ_   2
#define DM_    1024
#define QL_    2048
#define NH_    16
#define DH_    64
#define LOCAL_ 1000
#define SCALE_ 0.125f
#define RPAD_  2176
#define CML_   (0.125f * 1.44269504088896f)   // scale * log2(e)

// ---------------- scratch (__device__ globals; zero-initialized) ---------------
__device__ __align__(16) __half h_Wqkv[3*DM_*DM_];
__device__ __align__(16) __half h_Wr[DM_*DM_];
__device__ __align__(16) __half h_Wo[DM_*DM_];
__device__ __align__(16) __half h_Z[BSZ_*DM_*QL_];
__device__ __align__(16) __half h_Pe[DM_*QL_];
__device__ __align__(16) __half g_Qh[BSZ_*DM_*QL_];
__device__ __align__(16) __half g_Kh[BSZ_*DM_*QL_];
__device__ __align__(16) __half g_Vh[BSZ_*DM_*QL_];
__device__ __align__(16) __half g_Rh[DM_*RPAD_];
__device__ __align__(16) __half g_AVh[BSZ_*DM_*QL_];
__device__ __align__(16) float  g_TMP[BSZ_*DM_*QL_];

__device__ __forceinline__ uint32_t f22u(float a, float b) {
    __half2 h = __floats2half2_rn(a, b);
    return *reinterpret_cast<uint32_t*>(&h);
}
__device__ __forceinline__ uint32_t h2ex2(float a, float b) {
    uint32_t h = f22u(a, b), r;
    asm("ex2.approx.f16x2 %0, %1;" : "=r"(r) : "r"(h));
    return r;
}

#define MMA_F16(C, A, B)                                                        \
    asm volatile(                                                               \
        "mma.sync.aligned.m16n8k16.row.col.f32.f16.f16.f32 "                    \
        "{%0,%1,%2,%3}, {%4,%5,%6,%7}, {%8,%9}, {%0,%1,%2,%3};"                 \
        : "+f"((C)[0]), "+f"((C)[1]), "+f"((C)[2]), "+f"((C)[3])                \
        : "r"((A)[0]), "r"((A)[1]), "r"((A)[2]), "r"((A)[3]),                   \
          "r"((B)[0]), "r"((B)[1]))

#define LDSM4(R, addr)                                                          \
    asm volatile("ldmatrix.sync.aligned.m8n8.x4.shared.b16 {%0,%1,%2,%3}, [%4];"\
        : "=r"((R)[0]), "=r"((R)[1]), "=r"((R)[2]), "=r"((R)[3]) : "r"(addr))

#define LDSM4T(R, addr)                                                         \
    asm volatile("ldmatrix.sync.aligned.m8n8.x4.trans.shared.b16 {%0,%1,%2,%3}, [%4];"\
        : "=r"((R)[0]), "=r"((R)[1]), "=r"((R)[2]), "=r"((R)[3]) : "r"(addr))

#define CPA16(dst, src)                                                         \
    asm volatile("cp.async.cg.shared.global [%0], [%1], 16;" :: "r"(dst), "l"(src))
#define CP_COMMIT asm volatile("cp.async.commit_group;")
#define CP_WAIT0  asm volatile("cp.async.wait_group 0;" ::: "memory")

// ---------------- fused fp32 -> fp16 conversion (one launch) -------------------
#define F2H_N4 2883584
__global__ void f2h_all(const float* __restrict__ z, const float* __restrict__ pos,
                        const float* __restrict__ wqkv, const float* __restrict__ wr,
                        const float* __restrict__ wo)
{
    const int nW = 3*DM_*DM_/4, nR = DM_*DM_/4, nZ = BSZ_*DM_*QL_/4, nP = DM_*QL_/4;
    int off = blockIdx.x * blockDim.x + threadIdx.x;
    const float* src; __half* dst;
    if (off < nW)              { src = wqkv; dst = h_Wqkv; }
    else if ((off -= nW) < nR) { src = wr;   dst = h_Wr;  }
    else if ((off -= nR) < nR) { src = wo;   dst = h_Wo;  }
    else if ((off -= nR) < nZ) { src = z;    dst = h_Z;   }
    else if ((off -= nZ) < nP) { src = pos;  dst = h_Pe;  }
    else return;
    float4 v = ((const float4*)src)[off];
    uint2 o = { f22u(v.x, v.y), f22u(v.z, v.w) };
    ((uint2*)dst)[off] = o;
}

// =====================================================================
// fp16 GEMM, k-tile 64, 2-stage cp.async (420us-proven config)
// =====================================================================
#define GA_BUF 18432    // 128 x 72 halves
#define GB_BUF 17408    // 64 x 136 halves
#define GSTG   (GA_BUF + GB_BUF)
#define GEMM_SMEM (2 * GSTG)

__global__ void __launch_bounds__(256, 2) gemm_tc(
    const float* __restrict__ U, const float* __restrict__ bias, int K, int mode)
{
    extern __shared__ char smc[];
    const uint32_t sbase = (uint32_t)__cvta_generic_to_shared(smc);

    int emode, bb, my;
    if (mode == 3) {
        int y = blockIdx.y;
        if (y < 48) { emode = 0; bb = y / 24; my = y % 24; }
        else        { emode = 1; bb = 0;      my = y - 48; }
    } else { emode = 2; bb = blockIdx.z; my = blockIdx.y; }

    const int N = QL_;
    const __half* A = (emode == 0) ? h_Wqkv : (emode == 1) ? h_Wr : h_Wo;
    const __half* B = (emode == 0) ? h_Z + (size_t)bb * K * N
                    : (emode == 1) ? h_Pe
                    : g_AVh + (size_t)bb * DM_ * QL_;

    const int m0 = my * 128, n0 = blockIdx.x * 128;
    const int tid = threadIdx.x, lane = tid & 31, wid = tid >> 5;
    const int g = lane >> 2, q = lane & 3;
    const int wm = wid >> 2, wn = wid & 3;

    const int a_row = tid >> 1, a_h = (tid & 1) * 32;
    const int b_row = tid >> 2, b_h = (tid & 3) * 32;
    const __half* AgB = A + (size_t)(m0 + a_row) * K + a_h;
    const __half* BgB = B + (size_t)b_row * N + n0 + b_h;
    const uint32_t daB = sbase + (a_row * 72 + a_h) * 2;
    const uint32_t dbB = sbase + GA_BUF + (b_row * 136 + b_h) * 2;

    uint32_t a_addr[4], b_addr[2];
    #pragma unroll
    for (int tm = 0; tm < 4; tm++)
        a_addr[tm] = sbase + ((wm * 64 + tm * 16 + (lane & 15)) * 72 + (lane >> 4) * 8) * 2;
    #pragma unroll
    for (int p = 0; p < 2; p++)
        b_addr[p] = sbase + GA_BUF + ((lane & 15) * 136 + wn * 32 + p * 16 + (lane >> 4) * 8) * 2;

    float acc[4][4][4];
    #pragma unroll
    for (int i = 0; i < 4; i++)
        #pragma unroll
        for (int j = 0; j < 4; j++)
            #pragma unroll
            for (int c = 0; c < 4; c++) acc[i][j][c] = 0.0f;

    const int nt = K / 64;
    {
        CPA16(daB, AgB);      CPA16(daB + 16, AgB + 8);
        CPA16(daB + 32, AgB + 16); CPA16(daB + 48, AgB + 24);
        CPA16(dbB, BgB);      CPA16(dbB + 16, BgB + 8);
        CPA16(dbB + 32, BgB + 16); CPA16(dbB + 48, BgB + 24);
        CP_COMMIT;
    }

    for (int t = 0; t < nt; t++) {
        CP_WAIT0;
        __syncthreads();
        if (t + 1 < nt) {
            const int k1 = (t + 1) * 64;
            const uint32_t so = ((t + 1) & 1) * GSTG;
            const __half* as = AgB + k1;
            const __half* bs = BgB + (size_t)k1 * N;
            CPA16(daB + so, as);      CPA16(daB + so + 16, as + 8);
            CPA16(daB + so + 32, as + 16); CPA16(daB + so + 48, as + 24);
            CPA16(dbB + so, bs);      CPA16(dbB + so + 16, bs + 8);
            CPA16(dbB + so + 32, bs + 16); CPA16(dbB + so + 48, bs + 24);
            CP_COMMIT;
        }
        const uint32_t so = (t & 1) * GSTG;
        #pragma unroll
        for (int kk = 0; kk < 4; kk++) {
            uint32_t af[4][4], bt[2][4];
            #pragma unroll
            for (int tm = 0; tm < 4; tm++) LDSM4(af[tm], a_addr[tm] + so + kk * 32);
            #pragma unroll
            for (int p = 0; p < 2; p++)    LDSM4T(bt[p], b_addr[p] + so + kk * 16 * 136 * 2);
            #pragma unroll
            for (int tm = 0; tm < 4; tm++)
                #pragma unroll
                for (int tn = 0; tn < 4; tn++)
                    MMA_F16(acc[tm][tn], af[tm], &bt[tn >> 1][(tn & 1) * 2]);
        }
    }

    #pragma unroll
    for (int tm = 0; tm < 4; tm++) {
        #pragma unroll
        for (int half = 0; half < 2; half++) {
            const int m = m0 + wm * 64 + tm * 16 + g + half * 8;
            #pragma unroll
            for (int tn = 0; tn < 4; tn++) {
                const int n = n0 + wn * 32 + tn * 8 + 2 * q;
                float v0 = acc[tm][tn][half * 2 + 0];
                float v1 = acc[tm][tn][half * 2 + 1];
                if (emode == 0) {
                    const float2 u = *(const float2*)&U[((size_t)bb * 3 * DM_ + m) * QL_ + n];
                    v0 += u.x; v1 += u.y;
                    const int which = m >> 10, rem = m & 1023;
                    __half* dst = (which == 0) ? g_Qh : (which == 1) ? g_Kh : g_Vh;
                    *(uint32_t*)&dst[((size_t)bb * DM_ + rem) * QL_ + n] = f22u(v0, v1);
                } else if (emode == 1) {
                    *(uint32_t*)&g_Rh[(size_t)m * RPAD_ + n] = f22u(v0, v1);
                } else {
                    const float bbia = bias[m];
                    const float2 u = *(const float2*)&U[((size_t)bb * DM_ + m) * QL_ + n];
                    v0 += bbia + u.x; v1 += bbia + u.y;
                    *(float2*)&g_TMP[((size_t)bb * DM_ + m) * QL_ + n] = make_float2(v0, v1);
                }
            }
        }
    }
}

// =====================================================================
// fp16 attention: 8 warps = 4 row-groups x 2 j-halves.
// S/P/O register-resident; per-warp local softmax (exact via epilogue merge).
// 1 CTA barrier + 1 named pair-barrier per tile. ~106 KB smem, 2 CTA/SM.
// =====================================================================
#define H_QW 0
#define H_QR 9216
#define H_K  18432        // 2 x 9216  (64 x 72 halves)
#define H_V  36864        // 2 x 9216
#define H_R  55296        // 2 x 17408 (64 x 136 halves)
#define H_E  90112        // 64 x 136 halves
#define F_ML 107520       // sMw[8][16], sLw[8][16]
#define ATTN_SMEM (F_ML + 1024)

__global__ void __launch_bounds__(256, 2) attn_tc(
    const float* __restrict__ rwb_all, const float* __restrict__ rrb_all)
{
    extern __shared__ char smc[];
    const uint32_t sb = (uint32_t)__cvta_generic_to_shared(smc);
    __half* hQW = (__half*)(smc + H_QW);
    __half* hQR = (__half*)(smc + H_QR);
    __half* hE  = (__half*)(smc + H_E);
    float* sMw = (float*)(smc + F_ML);
    float* sLw = sMw + 128;

    const int b = blockIdx.z, n = blockIdx.y;
    const int i0 = blockIdx.x * 64;
    const int tid = threadIdx.x;
    const int lane = tid & 31, wid = tid >> 5;   // 0..7
    const int g = lane >> 2, q = lane & 3;
    const int wm = wid >> 1, wn = wid & 1;

    const __half* Qh = g_Qh + ((size_t)b * DM_ + n * DH_) * QL_;
    const __half* Kh = g_Kh + ((size_t)b * DM_ + n * DH_) * QL_;
    const __half* Vh = g_Vh + ((size_t)b * DM_ + n * DH_) * QL_;
    const __half* Rh = g_Rh + (size_t)(n * DH_) * RPAD_;

    // ---- Q staging: [d][i] -> [i][d] with biases ----
    for (int idx = tid; idx < 64 * 16; idx += 256) {
        int d = idx >> 4, ic = (idx & 15) * 4;
        uint2 u = *(const uint2*)&Qh[(size_t)d * QL_ + i0 + ic];
        float2 v01 = __half22float2(*(__half2*)&u.x);
        float2 v23 = __half22float2(*(__half2*)&u.y);
        float w = rwb_all[n * DH_ + d];
        float r = rrb_all[n * DH_ + d];
        float vv[4] = {v01.x, v01.y, v23.x, v23.y};
        #pragma unroll
        for (int c = 0; c < 4; c++) {
            hQW[(ic + c) * 72 + d] = __float2half_rn(vv[c] + w);
            hQR[(ic + c) * 72 + d] = __float2half_rn(vv[c] + r);
        }
    }

    // ---- cp.async mappings (256 threads) ----
    const int cp_row = tid >> 2;
    const int cp_kc = (tid & 3) * 2;
    const int cp_rc = (tid & 3) * 4;
    const uint32_t dK = sb + H_K + (cp_row * 72 + cp_kc * 8) * 2;
    const uint32_t dV = sb + H_V + (cp_row * 72 + cp_kc * 8) * 2;
    const uint32_t dR = sb + H_R + (cp_row * 136 + cp_rc * 8) * 2;
    const __half* sKg = Kh + (size_t)cp_row * QL_ + cp_kc * 8;
    const __half* sVg = Vh + (size_t)cp_row * QL_ + cp_kc * 8;
    const __half* sRg = Rh + (size_t)cp_row * RPAD_ + cp_rc * 8;

    // ---- ldmatrix base addresses ----
    const uint32_t qw_addr = sb + H_QW + ((16 * wm + (lane & 15)) * 72 + (lane >> 4) * 8) * 2;
    const uint32_t qr_addr = sb + H_QR + ((16 * wm + (lane & 15)) * 72 + (lane >> 4) * 8) * 2;
    const uint32_t k_addr  = sb + H_K + ((lane & 15) * 72 + 32 * wn + (lane >> 4) * 8) * 2;
    const uint32_t r_addr  = sb + H_R + ((lane & 15) * 136 + 64 * wn + (lane >> 4) * 8) * 2;
    const uint32_t v_addr  = sb + H_V + (((lane & 7) + (lane >> 4) * 8) * 72 + 32 * wn + ((lane >> 3) & 1) * 8) * 2;

    float accO[8][4];
    #pragma unroll
    for (int nb = 0; nb < 8; nb++)
        #pragma unroll
        for (int c = 0; c < 4; c++) accO[nb][c] = 0.0f;
    float m0r = -1e30f, m1r = -1e30f, l0r = 0.0f, l1r = 0.0f;

    const int r0l = 16 * wm + g, r1l = r0l + 8;
    const int gi0 = i0 + r0l, gi1 = i0 + r1l;

    int jlo = i0 - (LOCAL_ - 1); if (jlo < 0) jlo = 0; jlo &= ~63;
    const int ntile = (i0 - jlo) / 64 + 1;

    {   // prologue: K/V/R tile 0 -> buf 0
        const int rbase = jlo - i0 + (QL_ - 1) - 63;
        CPA16(dK, sKg + jlo); CPA16(dK + 16, sKg + jlo + 8);
        CPA16(dV, sVg + jlo); CPA16(dV + 16, sVg + jlo + 8);
        const __half* r0 = sRg + rbase;
        CPA16(dR, r0); CPA16(dR + 16, r0 + 8); CPA16(dR + 32, r0 + 16); CPA16(dR + 48, r0 + 24);
        CP_COMMIT;
    }

    for (int t = 0; t < ntile; t++) {
        const int j0 = jlo + t * 64;
        CP_WAIT0;
        __syncthreads();
        if (t + 1 < ntile) {
            const int j1 = j0 + 64;
            const int rb1 = j1 - i0 + (QL_ - 1) - 63;
            const uint32_t kb1 = ((t + 1) & 1) * 9216;
            const uint32_t rbb = ((t + 1) & 1) * 17408;
            CPA16(dK + kb1, sKg + j1); CPA16(dK + kb1 + 16, sKg + j1 + 8);
            CPA16(dV + kb1, sVg + j1); CPA16(dV + kb1 + 16, sVg + j1 + 8);
            const __half* r1 = sRg + rb1;
            CPA16(dR + rbb, r1); CPA16(dR + rbb + 16, r1 + 8);
            CPA16(dR + rbb + 32, r1 + 16); CPA16(dR + rbb + 48, r1 + 24);
            CP_COMMIT;
        }
        const uint32_t kb = (t & 1) * 9216;
        const uint32_t rb = (t & 1) * 17408;

        // ---- E = QR^T R (warp's 64-col half), spill to hE ----
        {
            float accE[8][4];
            #pragma unroll
            for (int nb = 0; nb < 8; nb++)
                #pragma unroll
                for (int c = 0; c < 4; c++) accE[nb][c] = 0.0f;
            #pragma unroll
            for (int kk = 0; kk < 4; kk++) {
                uint32_t ar[4], br[4][4];
                LDSM4(ar, qr_addr + kk * 32);
                #pragma unroll
                for (int p = 0; p < 4; p++)
                    LDSM4T(br[p], r_addr + rb + kk * 4352 + p * 32);
                #pragma unroll
                for (int nb = 0; nb < 8; nb++)
                    MMA_F16(accE[nb], ar, &br[nb >> 1][(nb & 1) * 2]);
            }
            #pragma unroll
            for (int nb = 0; nb < 8; nb++) {
                int col = 64 * wn + nb * 8 + 2 * q;
                *(uint32_t*)&hE[r0l * 136 + col] = f22u(accE[nb][0], accE[nb][1]);
                *(uint32_t*)&hE[r1l * 136 + col] = f22u(accE[nb][2], accE[nb][3]);
            }
        }
        // pair barrier: both wn warps of this wm finished writing their E halves
        asm volatile("bar.sync %0, %1;" :: "r"(wm + 1), "r"(64) : "memory");

        // ---- S = QW^T K (warp's 32-col half), registers ----
        float accS[4][4];
        #pragma unroll
        for (int nb = 0; nb < 4; nb++)
            #pragma unroll
            for (int c = 0; c < 4; c++) accS[nb][c] = 0.0f;
        #pragma unroll
        for (int kk = 0; kk < 4; kk++) {
            uint32_t aw[4], bk0[4], bk1[4];
            LDSM4(aw, qw_addr + kk * 32);
            LDSM4T(bk0, k_addr + kb + kk * 2304);
            LDSM4T(bk1, k_addr + kb + kk * 2304 + 32);
            MMA_F16(accS[0], aw, &bk0[0]);
            MMA_F16(accS[1], aw, &bk0[2]);
            MMA_F16(accS[2], aw, &bk1[0]);
            MMA_F16(accS[3], aw, &bk1[2]);
        }

        // ---- softmax (per-warp local max; exact via epilogue merge) ----
        uint32_t pw0[4], pw1[4];
        {
            const bool needmask = (j0 == i0) || (j0 <= i0 + 63 - LOCAL_);
            float rmax0 = -1e30f, rmax1 = -1e30f;
            #pragma unroll
            for (int nb = 0; nb < 4; nb++) {
                int c0 = 32 * wn + nb * 8 + 2 * q;
                float e00 = __half2float(hE[r0l * 136 + (c0 - r0l + 63)]);
                float e01 = __half2float(hE[r0l * 136 + (c0 - r0l + 64)]);
                float e10 = __half2float(hE[r1l * 136 + (c0 - r1l + 63)]);
                float e11 = __half2float(hE[r1l * 136 + (c0 - r1l + 64)]);
                float v00 = (accS[nb][0] + e00) * CML_;
                float v01 = (accS[nb][1] + e01) * CML_;
                float v10 = (accS[nb][2] + e10) * CML_;
                float v11 = (accS[nb][3] + e11) * CML_;
                if (needmask) {
                    int ja = j0 + c0, jb2 = ja + 1;
                    v00 = (ja  <= gi0 && ja  > gi0 - LOCAL_) ? v00 : -1e30f;
                    v01 = (jb2 <= gi0 && jb2 > gi0 - LOCAL_) ? v01 : -1e30f;
                    v10 = (ja  <= gi1 && ja  > gi1 - LOCAL_) ? v10 : -1e30f;
                    v11 = (jb2 <= gi1 && jb2 > gi1 - LOCAL_) ? v11 : -1e30f;
                }
                accS[nb][0] = v00; accS[nb][1] = v01;
                accS[nb][2] = v10; accS[nb][3] = v11;
                rmax0 = fmaxf(rmax0, fmaxf(v00, v01));
                rmax1 = fmaxf(rmax1, fmaxf(v10, v11));
            }
            rmax0 = fmaxf(rmax0, __shfl_xor_sync(0xffffffffu, rmax0, 1));
            rmax0 = fmaxf(rmax0, __shfl_xor_sync(0xffffffffu, rmax0, 2));
            rmax1 = fmaxf(rmax1, __shfl_xor_sync(0xffffffffu, rmax1, 1));
            rmax1 = fmaxf(rmax1, __shfl_xor_sync(0xffffffffu, rmax1, 2));
            float mn0 = fmaxf(m0r, rmax0), mn1 = fmaxf(m1r, rmax1);
            float cc0 = exp2f(m0r - mn0), cc1 = exp2f(m1r - mn1);

            float rs0 = 0.0f, rs1 = 0.0f;
            #pragma unroll
            for (int nb = 0; nb < 4; nb++) {
                pw0[nb] = h2ex2(accS[nb][0] - mn0, accS[nb][1] - mn0);
                pw1[nb] = h2ex2(accS[nb][2] - mn1, accS[nb][3] - mn1);
                float2 f0 = __half22float2(*(__half2*)&pw0[nb]);
                float2 f1 = __half22float2(*(__half2*)&pw1[nb]);
                rs0 += f0.x + f0.y;
                rs1 += f1.x + f1.y;
            }
            rs0 += __shfl_xor_sync(0xffffffffu, rs0, 1);
            rs0 += __shfl_xor_sync(0xffffffffu, rs0, 2);
            rs1 += __shfl_xor_sync(0xffffffffu, rs1, 1);
            rs1 += __shfl_xor_sync(0xffffffffu, rs1, 2);
            l0r = l0r * cc0 + rs0;
            l1r = l1r * cc1 + rs1;
            m0r = mn0; m1r = mn1;

            #pragma unroll
            for (int nb = 0; nb < 8; nb++) {
                accO[nb][0] *= cc0; accO[nb][1] *= cc0;
                accO[nb][2] *= cc1; accO[nb][3] *= cc1;
            }
        }

        // ---- PV over warp's j-half (k = 32): P from register repack ----
        #pragma unroll
        for (int kk = 0; kk < 2; kk++) {
            uint32_t ap[4] = { pw0[2 * kk], pw1[2 * kk], pw0[2 * kk + 1], pw1[2 * kk + 1] };
            #pragma unroll
            for (int p = 0; p < 4; p++) {
                uint32_t bv[4];
                LDSM4(bv, v_addr + kb + p * 2304 + kk * 32);
                MMA_F16(accO[2 * p],     ap, &bv[0]);
                MMA_F16(accO[2 * p + 1], ap, &bv[2]);
            }
        }
    }

    // ---- epilogue: merge wn halves (exact softmax), /L, store ----
    if (q == 0) {
        sMw[wid * 16 + g] = m0r;     sMw[wid * 16 + g + 8] = m1r;
        sLw[wid * 16 + g] = l0r;     sLw[wid * 16 + g + 8] = l1r;
    }
    __syncthreads();
    {
        float pm0 = sMw[(wid ^ 1) * 16 + g],     pl0 = sLw[(wid ^ 1) * 16 + g];
        float pm1 = sMw[(wid ^ 1) * 16 + g + 8], pl1 = sLw[(wid ^ 1) * 16 + g + 8];
        float M0 = fmaxf(m0r, pm0), M1 = fmaxf(m1r, pm1);
        float a0 = exp2f(m0r - M0), a1 = exp2f(m1r - M1);
        float L0 = l0r * a0 + pl0 * exp2f(pm0 - M0);
        float L1 = l1r * a1 + pl1 * exp2f(pm1 - M1);
        float s0 = a0 / L0, s1 = a1 / L1;

        float* fX = (float*)(smc + H_K) + wn * 4352;   // 64 x 68 fp32 per half
        #pragma unroll
        for (int nb = 0; nb < 8; nb++) {
            int d0 = nb * 8 + 2 * q;
            fX[(d0 + 0) * 68 + r0l] = accO[nb][0] * s0;
            fX[(d0 + 1) * 68 + r0l] = accO[nb][1] * s0;
            fX[(d0 + 0) * 68 + r1l] = accO[nb][2] * s1;
            fX[(d0 + 1) * 68 + r1l] = accO[nb][3] * s1;
        }
    }
    __syncthreads();
    {
        const float* fX0 = (const float*)(smc + H_K);
        const float* fX1 = fX0 + 4352;
        __half* AVh = g_AVh + ((size_t)b * DM_ + n * DH_) * QL_;
        for (int idx = tid; idx < 64 * 8; idx += 256) {
            int d = idx >> 3, ic = (idx & 7) * 8;
            const float* s0p = &fX0[d * 68 + ic];
            const float* s1p = &fX1[d * 68 + ic];
            uint4 o;
            o.x = f22u(s0p[0] + s1p[0], s0p[1] + s1p[1]);
            o.y = f22u(s0p[2] + s1p[2], s0p[3] + s1p[3]);
            o.z = f22u(s0p[4] + s1p[4], s0p[5] + s1p[5]);
            o.w = f22u(s0p[6] + s1p[6], s0p[7] + s1p[7]);
            *(uint4*)&AVh[(size_t)d * QL_ + i0 + ic] = o;
        }
    }
}

// ---------------- post-LN over d_model per (b, q) ------------------------------
__global__ void __launch_bounds__(256) ln_kernel(float* __restrict__ out)
{
    const int b  = blockIdx.y;
    const int tx = threadIdx.x & 31;
    const int ty = threadIdx.x >> 5;
    const int q  = blockIdx.x * 32 + tx;
    const float* X = g_TMP + (size_t)b * DM_ * QL_;

    float s = 0.0f, s2 = 0.0f;
    for (int o = ty; o < DM_; o += 8) {
        float v = X[(size_t)o * QL_ + q];
        s += v; s2 += v * v;
    }
    __shared__ float sh[8][32], sh2[8][32];
    __shared__ float mu[32], rs[32];
    sh[ty][tx] = s; sh2[ty][tx] = s2;
    __syncthreads();
    if (ty == 0) {
        float ts = 0.0f, ts2 = 0.0f;
        #pragma unroll
        for (int k = 0; k < 8; k++) { ts += sh[k][tx]; ts2 += sh2[k][tx]; }
        float m = ts * (1.0f / DM_);
        float var = ts2 * (1.0f / DM_) - m * m;
        mu[tx] = m;
        rs[tx] = rsqrtf(var + 1e-5f);
    }
    __syncthreads();
    float m = mu[tx], r = rs[tx];
    float* O = out + (size_t)b * DM_ * QL_;
    for (int o = ty; o < DM_; o += 8)
        O[(size_t)o * QL_ + q] = (X[(size_t)o * QL_ + q] - m) * r;
}

// ---------------- launch --------------------------------------------------------
extern "C" void kernel_launch(void* const* d_in, const int* in_sizes, int n_in,
                              void* d_out, int out_size)
{
    const float* z1ss = (const float*)d_in[0];
    const float* pos  = (const float*)d_in[1];
    const float* u1ss = (const float*)d_in[2];
    const float* Wqkv = (const float*)d_in[3];
    const float* Wr   = (const float*)d_in[4];
    const float* rwb  = (const float*)d_in[5];
    const float* rrb  = (const float*)d_in[6];
    const float* Wo   = (const float*)d_in[7];
    const float* bo   = (const float*)d_in[8];
    float* out = (float*)d_out;

    cudaFuncSetAttribute(gemm_tc, cudaFuncAttributeMaxDynamicSharedMemorySize, GEMM_SMEM);
    cudaFuncSetAttribute(attn_tc, cudaFuncAttributeMaxDynamicSharedMemorySize, ATTN_SMEM);

    f2h_all<<<(F2H_N4 + 255) / 256, 256>>>(z1ss, pos, Wqkv, Wr, Wo);

    dim3 g0(QL_ / 128, 56, 1);   // fused QKV (48 y-blocks) + Wr (8 y-blocks)
    gemm_tc<<<g0, 256, GEMM_SMEM>>>(u1ss, nullptr, DM_, 3);

    dim3 ga(QL_ / 64, NH_, BSZ_);
    attn_tc<<<ga, 256, ATTN_SMEM>>>(rwb, rrb);

    dim3 g2(QL_ / 128, DM_ / 128, BSZ_);
    gemm_tc<<<g2, 256, GEMM_SMEM>>>(z1ss, bo, DM_, 2);

    dim3 g3(QL_ / 32, BSZ_);
    ln_kernel<<<g3, 256>>>(out);
}

// round 14
// speedup vs baseline: 1.6244x; 1.1071x over previous
#include <cuda_runtime.h>
#include <cuda_fp16.h>
#include <cstdint>

#define BSZ_   2
#define DM_    1024
#define QL_    2048
#define NH_    16
#define DH_    64
#define LOCAL_ 1000
#define SCALE_ 0.125f
#define RPAD_  2176
#define CML_   (0.125f * 1.44269504088896f)   // scale * log2(e)

// ---------------- scratch (__device__ globals; zero-initialized) ---------------
__device__ __align__(16) __half h_Wqkv[3*DM_*DM_];
__device__ __align__(16) __half h_Wr[DM_*DM_];
__device__ __align__(16) __half h_Wo[DM_*DM_];
__device__ __align__(16) __half h_Z[BSZ_*DM_*QL_];
__device__ __align__(16) __half h_Pe[DM_*QL_];
__device__ __align__(16) __half g_Qh[BSZ_*DM_*QL_];
__device__ __align__(16) __half g_Kh[BSZ_*DM_*QL_];
__device__ __align__(16) __half g_Vh[BSZ_*DM_*QL_];
__device__ __align__(16) __half g_Rh[DM_*RPAD_];
__device__ __align__(16) __half g_AVh[BSZ_*DM_*QL_];
__device__ __align__(16) float  g_TMP[BSZ_*DM_*QL_];

__device__ __forceinline__ uint32_t f22u(float a, float b) {
    __half2 h = __floats2half2_rn(a, b);
    return *reinterpret_cast<uint32_t*>(&h);
}
__device__ __forceinline__ uint32_t h2ex2(float a, float b) {
    uint32_t h = f22u(a, b), r;
    asm("ex2.approx.f16x2 %0, %1;" : "=r"(r) : "r"(h));
    return r;
}

#define MMA_F16(C, A, B)                                                        \
    asm volatile(                                                               \
        "mma.sync.aligned.m16n8k16.row.col.f32.f16.f16.f32 "                    \
        "{%0,%1,%2,%3}, {%4,%5,%6,%7}, {%8,%9}, {%0,%1,%2,%3};"                 \
        : "+f"((C)[0]), "+f"((C)[1]), "+f"((C)[2]), "+f"((C)[3])                \
        : "r"((A)[0]), "r"((A)[1]), "r"((A)[2]), "r"((A)[3]),                   \
          "r"((B)[0]), "r"((B)[1]))

#define LDSM4(R, addr)                                                          \
    asm volatile("ldmatrix.sync.aligned.m8n8.x4.shared.b16 {%0,%1,%2,%3}, [%4];"\
        : "=r"((R)[0]), "=r"((R)[1]), "=r"((R)[2]), "=r"((R)[3]) : "r"(addr))

#define LDSM4T(R, addr)                                                         \
    asm volatile("ldmatrix.sync.aligned.m8n8.x4.trans.shared.b16 {%0,%1,%2,%3}, [%4];"\
        : "=r"((R)[0]), "=r"((R)[1]), "=r"((R)[2]), "=r"((R)[3]) : "r"(addr))

#define CPA16(dst, src)                                                         \
    asm volatile("cp.async.cg.shared.global [%0], [%1], 16;" :: "r"(dst), "l"(src))
#define CP_COMMIT asm volatile("cp.async.commit_group;")
#define CP_WAIT0  asm volatile("cp.async.wait_group 0;" ::: "memory")
#define CP_WAIT1  asm volatile("cp.async.wait_group 1;" ::: "memory")

// ---------------- fused fp32 -> fp16 conversion (one launch) -------------------
#define F2H_N4 2883584
__global__ void f2h_all(const float* __restrict__ z, const float* __restrict__ pos,
                        const float* __restrict__ wqkv, const float* __restrict__ wr,
                        const float* __restrict__ wo)
{
    const int nW = 3*DM_*DM_/4, nR = DM_*DM_/4, nZ = BSZ_*DM_*QL_/4, nP = DM_*QL_/4;
    int off = blockIdx.x * blockDim.x + threadIdx.x;
    const float* src; __half* dst;
    if (off < nW)              { src = wqkv; dst = h_Wqkv; }
    else if ((off -= nW) < nR) { src = wr;   dst = h_Wr;  }
    else if ((off -= nR) < nR) { src = wo;   dst = h_Wo;  }
    else if ((off -= nR) < nZ) { src = z;    dst = h_Z;   }
    else if ((off -= nZ) < nP) { src = pos;  dst = h_Pe;  }
    else return;
    float4 v = ((const float4*)src)[off];
    uint2 o = { f22u(v.x, v.y), f22u(v.z, v.w) };
    ((uint2*)dst)[off] = o;
}

// =====================================================================
// fp16 GEMM, 3-stage cp.async, k-tile 32 (best measured config)
// mode 3: fused QKV (+u1ss) + Wr;  mode 2: Wo
// =====================================================================
#define GA_BUF 10240
#define GB_BUF 8704
#define GSTG   (GA_BUF + GB_BUF)
#define GEMM_SMEM (3 * GSTG)

__global__ void __launch_bounds__(256, 2) gemm_tc(
    const float* __restrict__ U, const float* __restrict__ bias, int K, int mode)
{
    extern __shared__ char smc[];
    const uint32_t sbase = (uint32_t)__cvta_generic_to_shared(smc);

    int emode, bb, my;
    if (mode == 3) {
        int y = blockIdx.y;
        if (y < 48) { emode = 0; bb = y / 24; my = y % 24; }
        else        { emode = 1; bb = 0;      my = y - 48; }
    } else { emode = 2; bb = blockIdx.z; my = blockIdx.y; }

    const int N = QL_;
    const __half* A = (emode == 0) ? h_Wqkv : (emode == 1) ? h_Wr : h_Wo;
    const __half* B = (emode == 0) ? h_Z + (size_t)bb * K * N
                    : (emode == 1) ? h_Pe
                    : g_AVh + (size_t)bb * DM_ * QL_;

    const int m0 = my * 128, n0 = blockIdx.x * 128;
    const int tid = threadIdx.x, lane = tid & 31, wid = tid >> 5;
    const int g = lane >> 2, q = lane & 3;
    const int wm = wid >> 2, wn = wid & 3;

    const int a_row = tid >> 1, a_c = (tid & 1) * 2;
    const int b_row = tid >> 3, b_c = (tid & 7) * 2;
    const __half* AgB = A + (size_t)(m0 + a_row) * K + a_c * 8;
    const __half* BgB = B + (size_t)b_row * N + n0 + b_c * 8;
    const uint32_t daB = sbase + (a_row * 40 + a_c * 8) * 2;
    const uint32_t dbB = sbase + GA_BUF + (b_row * 136 + b_c * 8) * 2;

    uint32_t a_addr[4], b_addr[2];
    #pragma unroll
    for (int tm = 0; tm < 4; tm++)
        a_addr[tm] = sbase + ((wm * 64 + tm * 16 + (lane & 15)) * 40 + (lane >> 4) * 8) * 2;
    #pragma unroll
    for (int p = 0; p < 2; p++)
        b_addr[p] = sbase + GA_BUF + ((lane & 15) * 136 + wn * 32 + p * 16 + (lane >> 4) * 8) * 2;

    float acc[4][4][4];
    #pragma unroll
    for (int i = 0; i < 4; i++)
        #pragma unroll
        for (int j = 0; j < 4; j++)
            #pragma unroll
            for (int c = 0; c < 4; c++) acc[i][j][c] = 0.0f;

    const int nt = K / 32;
    #pragma unroll
    for (int t = 0; t < 2; t++) {
        const uint32_t so = t * GSTG;
        const __half* bs = BgB + (size_t)(t * 32) * N;
        CPA16(daB + so, AgB + t * 32); CPA16(daB + so + 16, AgB + t * 32 + 8);
        CPA16(dbB + so, bs);           CPA16(dbB + so + 16, bs + 8);
        CP_COMMIT;
    }

    int buf0 = 0, buf2 = 2;
    for (int t = 0; t < nt; t++) {
        CP_WAIT1;
        __syncthreads();
        if (t + 2 < nt) {
            const int k1 = (t + 2) * 32;
            const uint32_t so = buf2 * GSTG;
            const __half* bs = BgB + (size_t)k1 * N;
            CPA16(daB + so, AgB + k1); CPA16(daB + so + 16, AgB + k1 + 8);
            CPA16(dbB + so, bs);       CPA16(dbB + so + 16, bs + 8);
        }
        CP_COMMIT;
        const uint32_t so = buf0 * GSTG;
        #pragma unroll
        for (int kk = 0; kk < 2; kk++) {
            uint32_t af[4][4], bt[2][4];
            #pragma unroll
            for (int tm = 0; tm < 4; tm++) LDSM4(af[tm], a_addr[tm] + so + kk * 32);
            #pragma unroll
            for (int p = 0; p < 2; p++)    LDSM4T(bt[p], b_addr[p] + so + kk * 16 * 136 * 2);
            #pragma unroll
            for (int tm = 0; tm < 4; tm++)
                #pragma unroll
                for (int tn = 0; tn < 4; tn++)
                    MMA_F16(acc[tm][tn], af[tm], &bt[tn >> 1][(tn & 1) * 2]);
        }
        buf0 = (buf0 == 2) ? 0 : buf0 + 1;
        buf2 = (buf2 == 2) ? 0 : buf2 + 1;
    }

    #pragma unroll
    for (int tm = 0; tm < 4; tm++) {
        #pragma unroll
        for (int half = 0; half < 2; half++) {
            const int m = m0 + wm * 64 + tm * 16 + g + half * 8;
            #pragma unroll
            for (int tn = 0; tn < 4; tn++) {
                const int n = n0 + wn * 32 + tn * 8 + 2 * q;
                float v0 = acc[tm][tn][half * 2 + 0];
                float v1 = acc[tm][tn][half * 2 + 1];
                if (emode == 0) {
                    const float2 u = *(const float2*)&U[((size_t)bb * 3 * DM_ + m) * QL_ + n];
                    v0 += u.x; v1 += u.y;
                    const int which = m >> 10, rem = m & 1023;
                    __half* dst = (which == 0) ? g_Qh : (which == 1) ? g_Kh : g_Vh;
                    *(uint32_t*)&dst[((size_t)bb * DM_ + rem) * QL_ + n] = f22u(v0, v1);
                } else if (emode == 1) {
                    *(uint32_t*)&g_Rh[(size_t)m * RPAD_ + n] = f22u(v0, v1);
                } else {
                    const float bbia = bias[m];
                    const float2 u = *(const float2*)&U[((size_t)bb * DM_ + m) * QL_ + n];
                    v0 += bbia + u.x; v1 += bbia + u.y;
                    *(float2*)&g_TMP[((size_t)bb * DM_ + m) * QL_ + n] = make_float2(v0, v1);
                }
            }
        }
    }
}

// =====================================================================
// fp16 attention: 8 warps = 4 row-groups x 2 j-halves.
// S/P/O register-resident; per-warp local softmax (exact via epilogue merge).
// Trapezoidal E-skipping: row-group wm only needs E cols [48-16wm, 128-16wm).
// =====================================================================
#define H_QW 0
#define H_QR 9216
#define H_K  18432        // 2 x 9216  (64 x 72 halves)
#define H_V  36864        // 2 x 9216
#define H_R  55296        // 2 x 17408 (64 x 136 halves)
#define H_E  90112        // 64 x 136 halves
#define F_ML 107520       // sMw[8][16], sLw[8][16]
#define ATTN_SMEM (F_ML + 1024)

__global__ void __launch_bounds__(256, 2) attn_tc(
    const float* __restrict__ rwb_all, const float* __restrict__ rrb_all)
{
    extern __shared__ char smc[];
    const uint32_t sb = (uint32_t)__cvta_generic_to_shared(smc);
    __half* hQW = (__half*)(smc + H_QW);
    __half* hQR = (__half*)(smc + H_QR);
    __half* hE  = (__half*)(smc + H_E);
    float* sMw = (float*)(smc + F_ML);
    float* sLw = sMw + 128;

    const int b = blockIdx.z, n = blockIdx.y;
    const int i0 = blockIdx.x * 64;
    const int tid = threadIdx.x;
    const int lane = tid & 31, wid = tid >> 5;   // 0..7
    const int g = lane >> 2, q = lane & 3;
    const int wm = wid >> 1, wn = wid & 1;

    const __half* Qh = g_Qh + ((size_t)b * DM_ + n * DH_) * QL_;
    const __half* Kh = g_Kh + ((size_t)b * DM_ + n * DH_) * QL_;
    const __half* Vh = g_Vh + ((size_t)b * DM_ + n * DH_) * QL_;
    const __half* Rh = g_Rh + (size_t)(n * DH_) * RPAD_;

    // ---- Q staging: [d][i] -> [i][d] with biases ----
    for (int idx = tid; idx < 64 * 16; idx += 256) {
        int d = idx >> 4, ic = (idx & 15) * 4;
        uint2 u = *(const uint2*)&Qh[(size_t)d * QL_ + i0 + ic];
        float2 v01 = __half22float2(*(__half2*)&u.x);
        float2 v23 = __half22float2(*(__half2*)&u.y);
        float w = rwb_all[n * DH_ + d];
        float r = rrb_all[n * DH_ + d];
        float vv[4] = {v01.x, v01.y, v23.x, v23.y};
        #pragma unroll
        for (int c = 0; c < 4; c++) {
            hQW[(ic + c) * 72 + d] = __float2half_rn(vv[c] + w);
            hQR[(ic + c) * 72 + d] = __float2half_rn(vv[c] + r);
        }
    }

    // ---- cp.async mappings (256 threads) ----
    const int cp_row = tid >> 2;
    const int cp_kc = (tid & 3) * 2;
    const int cp_rc = (tid & 3) * 4;
    const uint32_t dK = sb + H_K + (cp_row * 72 + cp_kc * 8) * 2;
    const uint32_t dV = sb + H_V + (cp_row * 72 + cp_kc * 8) * 2;
    const uint32_t dR = sb + H_R + (cp_row * 136 + cp_rc * 8) * 2;
    const __half* sKg = Kh + (size_t)cp_row * QL_ + cp_kc * 8;
    const __half* sVg = Vh + (size_t)cp_row * QL_ + cp_kc * 8;
    const __half* sRg = Rh + (size_t)cp_row * RPAD_ + cp_rc * 8;

    // ---- ldmatrix base addresses ----
    const uint32_t qw_addr = sb + H_QW + ((16 * wm + (lane & 15)) * 72 + (lane >> 4) * 8) * 2;
    const uint32_t qr_addr = sb + H_QR + ((16 * wm + (lane & 15)) * 72 + (lane >> 4) * 8) * 2;
    const uint32_t k_addr  = sb + H_K + ((lane & 15) * 72 + 32 * wn + (lane >> 4) * 8) * 2;
    const uint32_t r_addr  = sb + H_R + ((lane & 15) * 136 + 64 * wn + (lane >> 4) * 8) * 2;
    const uint32_t v_addr  = sb + H_V + (((lane & 7) + (lane >> 4) * 8) * 72 + 32 * wn + ((lane >> 3) & 1) * 8) * 2;

    // trapezoidal E chunk bounds (16-col chunks within warp's 64-col half)
    const int p_lo = wn ? 0 : 3 - wm;
    const int p_hi = wn ? 3 - wm : 3;

    float accO[8][4];
    #pragma unroll
    for (int nb = 0; nb < 8; nb++)
        #pragma unroll
        for (int c = 0; c < 4; c++) accO[nb][c] = 0.0f;
    float m0r = -1e30f, m1r = -1e30f, l0r = 0.0f, l1r = 0.0f;

    const int r0l = 16 * wm + g, r1l = r0l + 8;
    const int gi0 = i0 + r0l, gi1 = i0 + r1l;

    int jlo = i0 - (LOCAL_ - 1); if (jlo < 0) jlo = 0; jlo &= ~63;
    const int ntile = (i0 - jlo) / 64 + 1;

    {   // prologue: K/V/R tile 0 -> buf 0
        const int rbase = jlo - i0 + (QL_ - 1) - 63;
        CPA16(dK, sKg + jlo); CPA16(dK + 16, sKg + jlo + 8);
        CPA16(dV, sVg + jlo); CPA16(dV + 16, sVg + jlo + 8);
        const __half* r0 = sRg + rbase;
        CPA16(dR, r0); CPA16(dR + 16, r0 + 8); CPA16(dR + 32, r0 + 16); CPA16(dR + 48, r0 + 24);
        CP_COMMIT;
    }

    for (int t = 0; t < ntile; t++) {
        const int j0 = jlo + t * 64;
        CP_WAIT0;
        __syncthreads();
        if (t + 1 < ntile) {
            const int j1 = j0 + 64;
            const int rb1 = j1 - i0 + (QL_ - 1) - 63;
            const uint32_t kb1 = ((t + 1) & 1) * 9216;
            const uint32_t rbb = ((t + 1) & 1) * 17408;
            CPA16(dK + kb1, sKg + j1); CPA16(dK + kb1 + 16, sKg + j1 + 8);
            CPA16(dV + kb1, sVg + j1); CPA16(dV + kb1 + 16, sVg + j1 + 8);
            const __half* r1 = sRg + rb1;
            CPA16(dR + rbb, r1); CPA16(dR + rbb + 16, r1 + 8);
            CPA16(dR + rbb + 32, r1 + 16); CPA16(dR + rbb + 48, r1 + 24);
            CP_COMMIT;
        }
        const uint32_t kb = (t & 1) * 9216;
        const uint32_t rb = (t & 1) * 17408;

        // ---- E = QR^T R (only the needed trapezoid chunks), spill to hE ----
        {
            float accE[8][4];
            #pragma unroll
            for (int nb = 0; nb < 8; nb++)
                #pragma unroll
                for (int c = 0; c < 4; c++) accE[nb][c] = 0.0f;
            #pragma unroll
            for (int kk = 0; kk < 4; kk++) {
                uint32_t ar[4];
                LDSM4(ar, qr_addr + kk * 32);
                #pragma unroll
                for (int p = 0; p < 4; p++) {
                    if (p >= p_lo && p <= p_hi) {      // warp-uniform
                        uint32_t br[4];
                        LDSM4T(br, r_addr + rb + kk * 4352 + p * 32);
                        MMA_F16(accE[2 * p],     ar, &br[0]);
                        MMA_F16(accE[2 * p + 1], ar, &br[2]);
                    }
                }
            }
            #pragma unroll
            for (int p = 0; p < 4; p++) {
                if (p >= p_lo && p <= p_hi) {
                    #pragma unroll
                    for (int e = 0; e < 2; e++) {
                        int nb = 2 * p + e;
                        int col = 64 * wn + nb * 8 + 2 * q;
                        *(uint32_t*)&hE[r0l * 136 + col] = f22u(accE[nb][0], accE[nb][1]);
                        *(uint32_t*)&hE[r1l * 136 + col] = f22u(accE[nb][2], accE[nb][3]);
                    }
                }
            }
        }
        // pair barrier: both wn warps of this wm finished writing their E chunks
        asm volatile("bar.sync %0, %1;" :: "r"(wm + 1), "r"(64) : "memory");

        // ---- S = QW^T K (warp's 32-col half), registers ----
        float accS[4][4];
        #pragma unroll
        for (int nb = 0; nb < 4; nb++)
            #pragma unroll
            for (int c = 0; c < 4; c++) accS[nb][c] = 0.0f;
        #pragma unroll
        for (int kk = 0; kk < 4; kk++) {
            uint32_t aw[4], bk0[4], bk1[4];
            LDSM4(aw, qw_addr + kk * 32);
            LDSM4T(bk0, k_addr + kb + kk * 2304);
            LDSM4T(bk1, k_addr + kb + kk * 2304 + 32);
            MMA_F16(accS[0], aw, &bk0[0]);
            MMA_F16(accS[1], aw, &bk0[2]);
            MMA_F16(accS[2], aw, &bk1[0]);
            MMA_F16(accS[3], aw, &bk1[2]);
        }

        // ---- softmax (per-warp local max; exact via epilogue merge) ----
        uint32_t pw0[4], pw1[4];
        {
            const bool needmask = (j0 == i0) || (j0 <= i0 + 63 - LOCAL_);
            float rmax0 = -1e30f, rmax1 = -1e30f;
            #pragma unroll
            for (int nb = 0; nb < 4; nb++) {
                int c0 = 32 * wn + nb * 8 + 2 * q;
                float e00 = __half2float(hE[r0l * 136 + (c0 - r0l + 63)]);
                float e01 = __half2float(hE[r0l * 136 + (c0 - r0l + 64)]);
                float e10 = __half2float(hE[r1l * 136 + (c0 - r1l + 63)]);
                float e11 = __half2float(hE[r1l * 136 + (c0 - r1l + 64)]);
                float v00 = (accS[nb][0] + e00) * CML_;
                float v01 = (accS[nb][1] + e01) * CML_;
                float v10 = (accS[nb][2] + e10) * CML_;
                float v11 = (accS[nb][3] + e11) * CML_;
                if (needmask) {
                    int ja = j0 + c0, jb2 = ja + 1;
                    v00 = (ja  <= gi0 && ja  > gi0 - LOCAL_) ? v00 : -1e30f;
                    v01 = (jb2 <= gi0 && jb2 > gi0 - LOCAL_) ? v01 : -1e30f;
                    v10 = (ja  <= gi1 && ja  > gi1 - LOCAL_) ? v10 : -1e30f;
                    v11 = (jb2 <= gi1 && jb2 > gi1 - LOCAL_) ? v11 : -1e30f;
                }
                accS[nb][0] = v00; accS[nb][1] = v01;
                accS[nb][2] = v10; accS[nb][3] = v11;
                rmax0 = fmaxf(rmax0, fmaxf(v00, v01));
                rmax1 = fmaxf(rmax1, fmaxf(v10, v11));
            }
            rmax0 = fmaxf(rmax0, __shfl_xor_sync(0xffffffffu, rmax0, 1));
            rmax0 = fmaxf(rmax0, __shfl_xor_sync(0xffffffffu, rmax0, 2));
            rmax1 = fmaxf(rmax1, __shfl_xor_sync(0xffffffffu, rmax1, 1));
            rmax1 = fmaxf(rmax1, __shfl_xor_sync(0xffffffffu, rmax1, 2));
            float mn0 = fmaxf(m0r, rmax0), mn1 = fmaxf(m1r, rmax1);
            float cc0 = exp2f(m0r - mn0), cc1 = exp2f(m1r - mn1);

            float rs0 = 0.0f, rs1 = 0.0f;
            #pragma unroll
            for (int nb = 0; nb < 4; nb++) {
                pw0[nb] = h2ex2(accS[nb][0] - mn0, accS[nb][1] - mn0);
                pw1[nb] = h2ex2(accS[nb][2] - mn1, accS[nb][3] - mn1);
                float2 f0 = __half22float2(*(__half2*)&pw0[nb]);
                float2 f1 = __half22float2(*(__half2*)&pw1[nb]);
                rs0 += f0.x + f0.y;
                rs1 += f1.x + f1.y;
            }
            rs0 += __shfl_xor_sync(0xffffffffu, rs0, 1);
            rs0 += __shfl_xor_sync(0xffffffffu, rs0, 2);
            rs1 += __shfl_xor_sync(0xffffffffu, rs1, 1);
            rs1 += __shfl_xor_sync(0xffffffffu, rs1, 2);
            l0r = l0r * cc0 + rs0;
            l1r = l1r * cc1 + rs1;
            m0r = mn0; m1r = mn1;

            #pragma unroll
            for (int nb = 0; nb < 8; nb++) {
                accO[nb][0] *= cc0; accO[nb][1] *= cc0;
                accO[nb][2] *= cc1; accO[nb][3] *= cc1;
            }
        }

        // ---- PV over warp's j-half (k = 32): P from register repack ----
        #pragma unroll
        for (int kk = 0; kk < 2; kk++) {
            uint32_t ap[4] = { pw0[2 * kk], pw1[2 * kk], pw0[2 * kk + 1], pw1[2 * kk + 1] };
            #pragma unroll
            for (int p = 0; p < 4; p++) {
                uint32_t bv[4];
                LDSM4(bv, v_addr + kb + p * 2304 + kk * 32);
                MMA_F16(accO[2 * p],     ap, &bv[0]);
                MMA_F16(accO[2 * p + 1], ap, &bv[2]);
            }
        }
    }

    // ---- epilogue: merge wn halves (exact softmax), /L, store ----
    if (q == 0) {
        sMw[wid * 16 + g] = m0r;     sMw[wid * 16 + g + 8] = m1r;
        sLw[wid * 16 + g] = l0r;     sLw[wid * 16 + g + 8] = l1r;
    }
    __syncthreads();
    {
        float pm0 = sMw[(wid ^ 1) * 16 + g],     pl0 = sLw[(wid ^ 1) * 16 + g];
        float pm1 = sMw[(wid ^ 1) * 16 + g + 8], pl1 = sLw[(wid ^ 1) * 16 + g + 8];
        float M0 = fmaxf(m0r, pm0), M1 = fmaxf(m1r, pm1);
        float a0 = exp2f(m0r - M0), a1 = exp2f(m1r - M1);
        float L0 = l0r * a0 + pl0 * exp2f(pm0 - M0);
        float L1 = l1r * a1 + pl1 * exp2f(pm1 - M1);
        float s0 = a0 / L0, s1 = a1 / L1;

        float* fX = (float*)(smc + H_K) + wn * 4352;   // 64 x 68 fp32 per half
        #pragma unroll
        for (int nb = 0; nb < 8; nb++) {
            int d0 = nb * 8 + 2 * q;
            fX[(d0 + 0) * 68 + r0l] = accO[nb][0] * s0;
            fX[(d0 + 1) * 68 + r0l] = accO[nb][1] * s0;
            fX[(d0 + 0) * 68 + r1l] = accO[nb][2] * s1;
            fX[(d0 + 1) * 68 + r1l] = accO[nb][3] * s1;
        }
    }
    __syncthreads();
    {
        const float* fX0 = (const float*)(smc + H_K);
        const float* fX1 = fX0 + 4352;
        __half* AVh = g_AVh + ((size_t)b * DM_ + n * DH_) * QL_;
        for (int idx = tid; idx < 64 * 8; idx += 256) {
            int d = idx >> 3, ic = (idx & 7) * 8;
            const float* s0p = &fX0[d * 68 + ic];
            const float* s1p = &fX1[d * 68 + ic];
            uint4 o;
            o.x = f22u(s0p[0] + s1p[0], s0p[1] + s1p[1]);
            o.y = f22u(s0p[2] + s1p[2], s0p[3] + s1p[3]);
            o.z = f22u(s0p[4] + s1p[4], s0p[5] + s1p[5]);
            o.w = f22u(s0p[6] + s1p[6], s0p[7] + s1p[7]);
            *(uint4*)&AVh[(size_t)d * QL_ + i0 + ic] = o;
        }
    }
}

// ---------------- post-LN over d_model per (b, q) ------------------------------
__global__ void __launch_bounds__(256) ln_kernel(float* __restrict__ out)
{
    const int b  = blockIdx.y;
    const int tx = threadIdx.x & 31;
    const int ty = threadIdx.x >> 5;
    const int q  = blockIdx.x * 32 + tx;
    const float* X = g_TMP + (size_t)b * DM_ * QL_;

    float s = 0.0f, s2 = 0.0f;
    for (int o = ty; o < DM_; o += 8) {
        float v = X[(size_t)o * QL_ + q];
        s += v; s2 += v * v;
    }
    __shared__ float sh[8][32], sh2[8][32];
    __shared__ float mu[32], rs[32];
    sh[ty][tx] = s; sh2[ty][tx] = s2;
    __syncthreads();
    if (ty == 0) {
        float ts = 0.0f, ts2 = 0.0f;
        #pragma unroll
        for (int k = 0; k < 8; k++) { ts += sh[k][tx]; ts2 += sh2[k][tx]; }
        float m = ts * (1.0f / DM_);
        float var = ts2 * (1.0f / DM_) - m * m;
        mu[tx] = m;
        rs[tx] = rsqrtf(var + 1e-5f);
    }
    __syncthreads();
    float m = mu[tx], r = rs[tx];
    float* O = out + (size_t)b * DM_ * QL_;
    for (int o = ty; o < DM_; o += 8)
        O[(size_t)o * QL_ + q] = (X[(size_t)o * QL_ + q] - m) * r;
}

// ---------------- launch --------------------------------------------------------
extern "C" void kernel_launch(void* const* d_in, const int* in_sizes, int n_in,
                              void* d_out, int out_size)
{
    const float* z1ss = (const float*)d_in[0];
    const float* pos  = (const float*)d_in[1];
    const float* u1ss = (const float*)d_in[2];
    const float* Wqkv = (const float*)d_in[3];
    const float* Wr   = (const float*)d_in[4];
    const float* rwb  = (const float*)d_in[5];
    const float* rrb  = (const float*)d_in[6];
    const float* Wo   = (const float*)d_in[7];
    const float* bo   = (const float*)d_in[8];
    float* out = (float*)d_out;

    cudaFuncSetAttribute(gemm_tc, cudaFuncAttributeMaxDynamicSharedMemorySize, GEMM_SMEM);
    cudaFuncSetAttribute(attn_tc, cudaFuncAttributeMaxDynamicSharedMemorySize, ATTN_SMEM);

    f2h_all<<<(F2H_N4 + 255) / 256, 256>>>(z1ss, pos, Wqkv, Wr, Wo);

    dim3 g0(QL_ / 128, 56, 1);   // fused QKV (48 y-blocks) + Wr (8 y-blocks)
    gemm_tc<<<g0, 256, GEMM_SMEM>>>(u1ss, nullptr, DM_, 3);

    dim3 ga(QL_ / 64, NH_, BSZ_);
    attn_tc<<<ga, 256, ATTN_SMEM>>>(rwb, rrb);

    dim3 g2(QL_ / 128, DM_ / 128, BSZ_);
    gemm_tc<<<g2, 256, GEMM_SMEM>>>(z1ss, bo, DM_, 2);

    dim3 g3(QL_ / 32, BSZ_);
    ln_kernel<<<g3, 256>>>(out);
}

// round 15
// speedup vs baseline: 1.6409x; 1.0102x over previous
#include <cuda_runtime.h>
#include <cuda_fp16.h>
#include <cstdint>

#define BSZ_   2
#define DM_    1024
#define QL_    2048
#define NH_    16
#define DH_    64
#define LOCAL_ 1000
#define SCALE_ 0.125f
#define RPAD_  2176
#define CML_   (0.125f * 1.44269504088896f)   // scale * log2(e)

// ---------------- scratch (__device__ globals; zero-initialized) ---------------
__device__ __align__(16) __half h_Wqkv[3*DM_*DM_];
__device__ __align__(16) __half h_Wr[DM_*DM_];
__device__ __align__(16) __half h_Wo[DM_*DM_];
__device__ __align__(16) __half h_Z[BSZ_*DM_*QL_];
__device__ __align__(16) __half h_Pe[DM_*QL_];
__device__ __align__(16) __half g_Qh[BSZ_*DM_*QL_];
__device__ __align__(16) __half g_Kh[BSZ_*DM_*QL_];
__device__ __align__(16) __half g_Vh[BSZ_*DM_*QL_];
__device__ __align__(16) __half g_Rh[DM_*RPAD_];
__device__ __align__(16) __half g_AVh[BSZ_*DM_*QL_];
__device__ __align__(16) float  g_TMP[BSZ_*DM_*QL_];

__device__ __forceinline__ uint32_t f22u(float a, float b) {
    __half2 h = __floats2half2_rn(a, b);
    return *reinterpret_cast<uint32_t*>(&h);
}
__device__ __forceinline__ uint32_t h2ex2(float a, float b) {
    uint32_t h = f22u(a, b), r;
    asm("ex2.approx.f16x2 %0, %1;" : "=r"(r) : "r"(h));
    return r;
}

#define MMA_F16(C, A, B)                                                        \
    asm volatile(                                                               \
        "mma.sync.aligned.m16n8k16.row.col.f32.f16.f16.f32 "                    \
        "{%0,%1,%2,%3}, {%4,%5,%6,%7}, {%8,%9}, {%0,%1,%2,%3};"                 \
        : "+f"((C)[0]), "+f"((C)[1]), "+f"((C)[2]), "+f"((C)[3])                \
        : "r"((A)[0]), "r"((A)[1]), "r"((A)[2]), "r"((A)[3]),                   \
          "r"((B)[0]), "r"((B)[1]))

#define LDSM4(R, addr)                                                          \
    asm volatile("ldmatrix.sync.aligned.m8n8.x4.shared.b16 {%0,%1,%2,%3}, [%4];"\
        : "=r"((R)[0]), "=r"((R)[1]), "=r"((R)[2]), "=r"((R)[3]) : "r"(addr))

#define LDSM4T(R, addr)                                                         \
    asm volatile("ldmatrix.sync.aligned.m8n8.x4.trans.shared.b16 {%0,%1,%2,%3}, [%4];"\
        : "=r"((R)[0]), "=r"((R)[1]), "=r"((R)[2]), "=r"((R)[3]) : "r"(addr))

#define CPA16(dst, src)                                                         \
    asm volatile("cp.async.cg.shared.global [%0], [%1], 16;" :: "r"(dst), "l"(src))
#define CP_COMMIT asm volatile("cp.async.commit_group;")
#define CP_WAIT0  asm volatile("cp.async.wait_group 0;" ::: "memory")
#define CP_WAIT2  asm volatile("cp.async.wait_group 2;" ::: "memory")

// ---------------- fused fp32 -> fp16 conversion (one launch) -------------------
#define F2H_N4 2883584
__global__ void f2h_all(const float* __restrict__ z, const float* __restrict__ pos,
                        const float* __restrict__ wqkv, const float* __restrict__ wr,
                        const float* __restrict__ wo)
{
    const int nW = 3*DM_*DM_/4, nR = DM_*DM_/4, nZ = BSZ_*DM_*QL_/4, nP = DM_*QL_/4;
    int off = blockIdx.x * blockDim.x + threadIdx.x;
    const float* src; __half* dst;
    if (off < nW)              { src = wqkv; dst = h_Wqkv; }
    else if ((off -= nW) < nR) { src = wr;   dst = h_Wr;  }
    else if ((off -= nR) < nR) { src = wo;   dst = h_Wo;  }
    else if ((off -= nR) < nZ) { src = z;    dst = h_Z;   }
    else if ((off -= nZ) < nP) { src = pos;  dst = h_Pe;  }
    else return;
    float4 v = ((const float4*)src)[off];
    uint2 o = { f22u(v.x, v.y), f22u(v.z, v.w) };
    ((uint2*)dst)[off] = o;
}

// =====================================================================
// fp16 GEMM, 4-stage cp.async, k-tile 32 (two full tiles in flight)
// mode 3: fused QKV (+u1ss) + Wr;  mode 2: Wo
// =====================================================================
#define GA_BUF 10240
#define GB_BUF 8704
#define GSTG   (GA_BUF + GB_BUF)
#define GEMM_SMEM (4 * GSTG)

__global__ void __launch_bounds__(256, 2) gemm_tc(
    const float* __restrict__ U, const float* __restrict__ bias, int K, int mode)
{
    extern __shared__ char smc[];
    const uint32_t sbase = (uint32_t)__cvta_generic_to_shared(smc);

    int emode, bb, my;
    if (mode == 3) {
        int y = blockIdx.y;
        if (y < 48) { emode = 0; bb = y / 24; my = y % 24; }
        else        { emode = 1; bb = 0;      my = y - 48; }
    } else { emode = 2; bb = blockIdx.z; my = blockIdx.y; }

    const int N = QL_;
    const __half* A = (emode == 0) ? h_Wqkv : (emode == 1) ? h_Wr : h_Wo;
    const __half* B = (emode == 0) ? h_Z + (size_t)bb * K * N
                    : (emode == 1) ? h_Pe
                    : g_AVh + (size_t)bb * DM_ * QL_;

    const int m0 = my * 128, n0 = blockIdx.x * 128;
    const int tid = threadIdx.x, lane = tid & 31, wid = tid >> 5;
    const int g = lane >> 2, q = lane & 3;
    const int wm = wid >> 2, wn = wid & 3;

    const int a_row = tid >> 1, a_c = (tid & 1) * 2;
    const int b_row = tid >> 3, b_c = (tid & 7) * 2;
    const __half* AgB = A + (size_t)(m0 + a_row) * K + a_c * 8;
    const __half* BgB = B + (size_t)b_row * N + n0 + b_c * 8;
    const uint32_t daB = sbase + (a_row * 40 + a_c * 8) * 2;
    const uint32_t dbB = sbase + GA_BUF + (b_row * 136 + b_c * 8) * 2;

    uint32_t a_addr[4], b_addr[2];
    #pragma unroll
    for (int tm = 0; tm < 4; tm++)
        a_addr[tm] = sbase + ((wm * 64 + tm * 16 + (lane & 15)) * 40 + (lane >> 4) * 8) * 2;
    #pragma unroll
    for (int p = 0; p < 2; p++)
        b_addr[p] = sbase + GA_BUF + ((lane & 15) * 136 + wn * 32 + p * 16 + (lane >> 4) * 8) * 2;

    float acc[4][4][4];
    #pragma unroll
    for (int i = 0; i < 4; i++)
        #pragma unroll
        for (int j = 0; j < 4; j++)
            #pragma unroll
            for (int c = 0; c < 4; c++) acc[i][j][c] = 0.0f;

    const int nt = K / 32;
    #pragma unroll
    for (int t = 0; t < 3; t++) {
        const uint32_t so = t * GSTG;
        const __half* bs = BgB + (size_t)(t * 32) * N;
        CPA16(daB + so, AgB + t * 32); CPA16(daB + so + 16, AgB + t * 32 + 8);
        CPA16(dbB + so, bs);           CPA16(dbB + so + 16, bs + 8);
        CP_COMMIT;
    }

    for (int t = 0; t < nt; t++) {
        CP_WAIT2;
        __syncthreads();
        if (t + 3 < nt) {
            const int k1 = (t + 3) * 32;
            const uint32_t so = ((t + 3) & 3) * GSTG;
            const __half* bs = BgB + (size_t)k1 * N;
            CPA16(daB + so, AgB + k1); CPA16(daB + so + 16, AgB + k1 + 8);
            CPA16(dbB + so, bs);       CPA16(dbB + so + 16, bs + 8);
        }
        CP_COMMIT;
        const uint32_t so = (t & 3) * GSTG;
        #pragma unroll
        for (int kk = 0; kk < 2; kk++) {
            uint32_t af[4][4], bt[2][4];
            #pragma unroll
            for (int tm = 0; tm < 4; tm++) LDSM4(af[tm], a_addr[tm] + so + kk * 32);
            #pragma unroll
            for (int p = 0; p < 2; p++)    LDSM4T(bt[p], b_addr[p] + so + kk * 16 * 136 * 2);
            #pragma unroll
            for (int tm = 0; tm < 4; tm++)
                #pragma unroll
                for (int tn = 0; tn < 4; tn++)
                    MMA_F16(acc[tm][tn], af[tm], &bt[tn >> 1][(tn & 1) * 2]);
        }
    }

    #pragma unroll
    for (int tm = 0; tm < 4; tm++) {
        #pragma unroll
        for (int half = 0; half < 2; half++) {
            const int m = m0 + wm * 64 + tm * 16 + g + half * 8;
            #pragma unroll
            for (int tn = 0; tn < 4; tn++) {
                const int n = n0 + wn * 32 + tn * 8 + 2 * q;
                float v0 = acc[tm][tn][half * 2 + 0];
                float v1 = acc[tm][tn][half * 2 + 1];
                if (emode == 0) {
                    const float2 u = *(const float2*)&U[((size_t)bb * 3 * DM_ + m) * QL_ + n];
                    v0 += u.x; v1 += u.y;
                    const int which = m >> 10, rem = m & 1023;
                    __half* dst = (which == 0) ? g_Qh : (which == 1) ? g_Kh : g_Vh;
                    *(uint32_t*)&dst[((size_t)bb * DM_ + rem) * QL_ + n] = f22u(v0, v1);
                } else if (emode == 1) {
                    *(uint32_t*)&g_Rh[(size_t)m * RPAD_ + n] = f22u(v0, v1);
                } else {
                    const float bbia = bias[m];
                    const float2 u = *(const float2*)&U[((size_t)bb * DM_ + m) * QL_ + n];
                    v0 += bbia + u.x; v1 += bbia + u.y;
                    *(float2*)&g_TMP[((size_t)bb * DM_ + m) * QL_ + n] = make_float2(v0, v1);
                }
            }
        }
    }
}

// =====================================================================
// fp16 attention: 8 warps = 4 row-groups x 2 j-halves.
// S/P/O register-resident; per-warp local softmax (exact via epilogue merge).
// Trapezoidal E-skipping; heavy CTAs (high i0) launch first.
// =====================================================================
#define H_QW 0
#define H_QR 9216
#define H_K  18432        // 2 x 9216  (64 x 72 halves)
#define H_V  36864        // 2 x 9216
#define H_R  55296        // 2 x 17408 (64 x 136 halves)
#define H_E  90112        // 64 x 136 halves
#define F_ML 107520       // sMw[8][16], sLw[8][16]
#define ATTN_SMEM (F_ML + 1024)

__global__ void __launch_bounds__(256, 2) attn_tc(
    const float* __restrict__ rwb_all, const float* __restrict__ rrb_all)
{
    extern __shared__ char smc[];
    const uint32_t sb = (uint32_t)__cvta_generic_to_shared(smc);
    __half* hQW = (__half*)(smc + H_QW);
    __half* hQR = (__half*)(smc + H_QR);
    __half* hE  = (__half*)(smc + H_E);
    float* sMw = (float*)(smc + F_ML);
    float* sLw = sMw + 128;

    const int b = blockIdx.z, n = blockIdx.y;
    const int i0 = (gridDim.x - 1 - blockIdx.x) * 64;   // heavy blocks first
    const int tid = threadIdx.x;
    const int lane = tid & 31, wid = tid >> 5;   // 0..7
    const int g = lane >> 2, q = lane & 3;
    const int wm = wid >> 1, wn = wid & 1;

    const __half* Qh = g_Qh + ((size_t)b * DM_ + n * DH_) * QL_;
    const __half* Kh = g_Kh + ((size_t)b * DM_ + n * DH_) * QL_;
    const __half* Vh = g_Vh + ((size_t)b * DM_ + n * DH_) * QL_;
    const __half* Rh = g_Rh + (size_t)(n * DH_) * RPAD_;

    // ---- Q staging: [d][i] -> [i][d] with biases ----
    for (int idx = tid; idx < 64 * 16; idx += 256) {
        int d = idx >> 4, ic = (idx & 15) * 4;
        uint2 u = *(const uint2*)&Qh[(size_t)d * QL_ + i0 + ic];
        float2 v01 = __half22float2(*(__half2*)&u.x);
        float2 v23 = __half22float2(*(__half2*)&u.y);
        float w = rwb_all[n * DH_ + d];
        float r = rrb_all[n * DH_ + d];
        float vv[4] = {v01.x, v01.y, v23.x, v23.y};
        #pragma unroll
        for (int c = 0; c < 4; c++) {
            hQW[(ic + c) * 72 + d] = __float2half_rn(vv[c] + w);
            hQR[(ic + c) * 72 + d] = __float2half_rn(vv[c] + r);
        }
    }

    // ---- cp.async mappings (256 threads) ----
    const int cp_row = tid >> 2;
    const int cp_kc = (tid & 3) * 2;
    const int cp_rc = (tid & 3) * 4;
    const uint32_t dK = sb + H_K + (cp_row * 72 + cp_kc * 8) * 2;
    const uint32_t dV = sb + H_V + (cp_row * 72 + cp_kc * 8) * 2;
    const uint32_t dR = sb + H_R + (cp_row * 136 + cp_rc * 8) * 2;
    const __half* sKg = Kh + (size_t)cp_row * QL_ + cp_kc * 8;
    const __half* sVg = Vh + (size_t)cp_row * QL_ + cp_kc * 8;
    const __half* sRg = Rh + (size_t)cp_row * RPAD_ + cp_rc * 8;

    // ---- ldmatrix base addresses ----
    const uint32_t qw_addr = sb + H_QW + ((16 * wm + (lane & 15)) * 72 + (lane >> 4) * 8) * 2;
    const uint32_t qr_addr = sb + H_QR + ((16 * wm + (lane & 15)) * 72 + (lane >> 4) * 8) * 2;
    const uint32_t k_addr  = sb + H_K + ((lane & 15) * 72 + 32 * wn + (lane >> 4) * 8) * 2;
    const uint32_t r_addr  = sb + H_R + ((lane & 15) * 136 + 64 * wn + (lane >> 4) * 8) * 2;
    const uint32_t v_addr  = sb + H_V + (((lane & 7) + (lane >> 4) * 8) * 72 + 32 * wn + ((lane >> 3) & 1) * 8) * 2;

    // trapezoidal E chunk bounds (16-col chunks within warp's 64-col half)
    const int p_lo = wn ? 0 : 3 - wm;
    const int p_hi = wn ? 3 - wm : 3;

    float accO[8][4];
    #pragma unroll
    for (int nb = 0; nb < 8; nb++)
        #pragma unroll
        for (int c = 0; c < 4; c++) accO[nb][c] = 0.0f;
    float m0r = -1e30f, m1r = -1e30f, l0r = 0.0f, l1r = 0.0f;

    const int r0l = 16 * wm + g, r1l = r0l + 8;
    const int gi0 = i0 + r0l, gi1 = i0 + r1l;

    int jlo = i0 - (LOCAL_ - 1); if (jlo < 0) jlo = 0; jlo &= ~63;
    const int ntile = (i0 - jlo) / 64 + 1;

    {   // prologue: K/V/R tile 0 -> buf 0
        const int rbase = jlo - i0 + (QL_ - 1) - 63;
        CPA16(dK, sKg + jlo); CPA16(dK + 16, sKg + jlo + 8);
        CPA16(dV, sVg + jlo); CPA16(dV + 16, sVg + jlo + 8);
        const __half* r0 = sRg + rbase;
        CPA16(dR, r0); CPA16(dR + 16, r0 + 8); CPA16(dR + 32, r0 + 16); CPA16(dR + 48, r0 + 24);
        CP_COMMIT;
    }

    for (int t = 0; t < ntile; t++) {
        const int j0 = jlo + t * 64;
        CP_WAIT0;
        __syncthreads();
        if (t + 1 < ntile) {
            const int j1 = j0 + 64;
            const int rb1 = j1 - i0 + (QL_ - 1) - 63;
            const uint32_t kb1 = ((t + 1) & 1) * 9216;
            const uint32_t rbb = ((t + 1) & 1) * 17408;
            CPA16(dK + kb1, sKg + j1); CPA16(dK + kb1 + 16, sKg + j1 + 8);
            CPA16(dV + kb1, sVg + j1); CPA16(dV + kb1 + 16, sVg + j1 + 8);
            const __half* r1 = sRg + rb1;
            CPA16(dR + rbb, r1); CPA16(dR + rbb + 16, r1 + 8);
            CPA16(dR + rbb + 32, r1 + 16); CPA16(dR + rbb + 48, r1 + 24);
            CP_COMMIT;
        }
        const uint32_t kb = (t & 1) * 9216;
        const uint32_t rb = (t & 1) * 17408;

        // ---- E = QR^T R (only the needed trapezoid chunks), spill to hE ----
        {
            float accE[8][4];
            #pragma unroll
            for (int nb = 0; nb < 8; nb++)
                #pragma unroll
                for (int c = 0; c < 4; c++) accE[nb][c] = 0.0f;
            #pragma unroll
            for (int kk = 0; kk < 4; kk++) {
                uint32_t ar[4];
                LDSM4(ar, qr_addr + kk * 32);
                #pragma unroll
                for (int p = 0; p < 4; p++) {
                    if (p >= p_lo && p <= p_hi) {      // warp-uniform
                        uint32_t br[4];
                        LDSM4T(br, r_addr + rb + kk * 4352 + p * 32);
                        MMA_F16(accE[2 * p],     ar, &br[0]);
                        MMA_F16(accE[2 * p + 1], ar, &br[2]);
                    }
                }
            }
            #pragma unroll
            for (int p = 0; p < 4; p++) {
                if (p >= p_lo && p <= p_hi) {
                    #pragma unroll
                    for (int e = 0; e < 2; e++) {
                        int nb = 2 * p + e;
                        int col = 64 * wn + nb * 8 + 2 * q;
                        *(uint32_t*)&hE[r0l * 136 + col] = f22u(accE[nb][0], accE[nb][1]);
                        *(uint32_t*)&hE[r1l * 136 + col] = f22u(accE[nb][2], accE[nb][3]);
                    }
                }
            }
        }
        // pair barrier: both wn warps of this wm finished writing their E chunks
        asm volatile("bar.sync %0, %1;" :: "r"(wm + 1), "r"(64) : "memory");

        // ---- S = QW^T K (warp's 32-col half), registers ----
        float accS[4][4];
        #pragma unroll
        for (int nb = 0; nb < 4; nb++)
            #pragma unroll
            for (int c = 0; c < 4; c++) accS[nb][c] = 0.0f;
        #pragma unroll
        for (int kk = 0; kk < 4; kk++) {
            uint32_t aw[4], bk0[4], bk1[4];
            LDSM4(aw, qw_addr + kk * 32);
            LDSM4T(bk0, k_addr + kb + kk * 2304);
            LDSM4T(bk1, k_addr + kb + kk * 2304 + 32);
            MMA_F16(accS[0], aw, &bk0[0]);
            MMA_F16(accS[1], aw, &bk0[2]);
            MMA_F16(accS[2], aw, &bk1[0]);
            MMA_F16(accS[3], aw, &bk1[2]);
        }

        // ---- softmax (per-warp local max; exact via epilogue merge) ----
        uint32_t pw0[4], pw1[4];
        {
            const bool needmask = (j0 == i0) || (j0 <= i0 + 63 - LOCAL_);
            float rmax0 = -1e30f, rmax1 = -1e30f;
            #pragma unroll
            for (int nb = 0; nb < 4; nb++) {
                int c0 = 32 * wn + nb * 8 + 2 * q;
                float e00 = __half2float(hE[r0l * 136 + (c0 - r0l + 63)]);
                float e01 = __half2float(hE[r0l * 136 + (c0 - r0l + 64)]);
                float e10 = __half2float(hE[r1l * 136 + (c0 - r1l + 63)]);
                float e11 = __half2float(hE[r1l * 136 + (c0 - r1l + 64)]);
                float v00 = (accS[nb][0] + e00) * CML_;
                float v01 = (accS[nb][1] + e01) * CML_;
                float v10 = (accS[nb][2] + e10) * CML_;
                float v11 = (accS[nb][3] + e11) * CML_;
                if (needmask) {
                    int ja = j0 + c0, jb2 = ja + 1;
                    v00 = (ja  <= gi0 && ja  > gi0 - LOCAL_) ? v00 : -1e30f;
                    v01 = (jb2 <= gi0 && jb2 > gi0 - LOCAL_) ? v01 : -1e30f;
                    v10 = (ja  <= gi1 && ja  > gi1 - LOCAL_) ? v10 : -1e30f;
                    v11 = (jb2 <= gi1 && jb2 > gi1 - LOCAL_) ? v11 : -1e30f;
                }
                accS[nb][0] = v00; accS[nb][1] = v01;
                accS[nb][2] = v10; accS[nb][3] = v11;
                rmax0 = fmaxf(rmax0, fmaxf(v00, v01));
                rmax1 = fmaxf(rmax1, fmaxf(v10, v11));
            }
            rmax0 = fmaxf(rmax0, __shfl_xor_sync(0xffffffffu, rmax0, 1));
            rmax0 = fmaxf(rmax0, __shfl_xor_sync(0xffffffffu, rmax0, 2));
            rmax1 = fmaxf(rmax1, __shfl_xor_sync(0xffffffffu, rmax1, 1));
            rmax1 = fmaxf(rmax1, __shfl_xor_sync(0xffffffffu, rmax1, 2));
            float mn0 = fmaxf(m0r, rmax0), mn1 = fmaxf(m1r, rmax1);
            float cc0 = exp2f(m0r - mn0), cc1 = exp2f(m1r - mn1);

            float rs0 = 0.0f, rs1 = 0.0f;
            #pragma unroll
            for (int nb = 0; nb < 4; nb++) {
                pw0[nb] = h2ex2(accS[nb][0] - mn0, accS[nb][1] - mn0);
                pw1[nb] = h2ex2(accS[nb][2] - mn1, accS[nb][3] - mn1);
                float2 f0 = __half22float2(*(__half2*)&pw0[nb]);
                float2 f1 = __half22float2(*(__half2*)&pw1[nb]);
                rs0 += f0.x + f0.y;
                rs1 += f1.x + f1.y;
            }
            rs0 += __shfl_xor_sync(0xffffffffu, rs0, 1);
            rs0 += __shfl_xor_sync(0xffffffffu, rs0, 2);
            rs1 += __shfl_xor_sync(0xffffffffu, rs1, 1);
            rs1 += __shfl_xor_sync(0xffffffffu, rs1, 2);
            l0r = l0r * cc0 + rs0;
            l1r = l1r * cc1 + rs1;
            m0r = mn0; m1r = mn1;

            #pragma unroll
            for (int nb = 0; nb < 8; nb++) {
                accO[nb][0] *= cc0; accO[nb][1] *= cc0;
                accO[nb][2] *= cc1; accO[nb][3] *= cc1;
            }
        }

        // ---- PV over warp's j-half (k = 32): P from register repack ----
        #pragma unroll
        for (int kk = 0; kk < 2; kk++) {
            uint32_t ap[4] = { pw0[2 * kk], pw1[2 * kk], pw0[2 * kk + 1], pw1[2 * kk + 1] };
            #pragma unroll
            for (int p = 0; p < 4; p++) {
                uint32_t bv[4];
                LDSM4(bv, v_addr + kb + p * 2304 + kk * 32);
                MMA_F16(accO[2 * p],     ap, &bv[0]);
                MMA_F16(accO[2 * p + 1], ap, &bv[2]);
            }
        }
    }

    // ---- epilogue: merge wn halves (exact softmax), /L, store ----
    if (q == 0) {
        sMw[wid * 16 + g] = m0r;     sMw[wid * 16 + g + 8] = m1r;
        sLw[wid * 16 + g] = l0r;     sLw[wid * 16 + g + 8] = l1r;
    }
    __syncthreads();
    {
        float pm0 = sMw[(wid ^ 1) * 16 + g],     pl0 = sLw[(wid ^ 1) * 16 + g];
        float pm1 = sMw[(wid ^ 1) * 16 + g + 8], pl1 = sLw[(wid ^ 1) * 16 + g + 8];
        float M0 = fmaxf(m0r, pm0), M1 = fmaxf(m1r, pm1);
        float a0 = exp2f(m0r - M0), a1 = exp2f(m1r - M1);
        float L0 = l0r * a0 + pl0 * exp2f(pm0 - M0);
        float L1 = l1r * a1 + pl1 * exp2f(pm1 - M1);
        float s0 = a0 / L0, s1 = a1 / L1;

        float* fX = (float*)(smc + H_K) + wn * 4352;   // 64 x 68 fp32 per half
        #pragma unroll
        for (int nb = 0; nb < 8; nb++) {
            int d0 = nb * 8 + 2 * q;
            fX[(d0 + 0) * 68 + r0l] = accO[nb][0] * s0;
            fX[(d0 + 1) * 68 + r0l] = accO[nb][1] * s0;
            fX[(d0 + 0) * 68 + r1l] = accO[nb][2] * s1;
            fX[(d0 + 1) * 68 + r1l] = accO[nb][3] * s1;
        }
    }
    __syncthreads();
    {
        const float* fX0 = (const float*)(smc + H_K);
        const float* fX1 = fX0 + 4352;
        __half* AVh = g_AVh + ((size_t)b * DM_ + n * DH_) * QL_;
        for (int idx = tid; idx < 64 * 8; idx += 256) {
            int d = idx >> 3, ic = (idx & 7) * 8;
            const float* s0p = &fX0[d * 68 + ic];
            const float* s1p = &fX1[d * 68 + ic];
            uint4 o;
            o.x = f22u(s0p[0] + s1p[0], s0p[1] + s1p[1]);
            o.y = f22u(s0p[2] + s1p[2], s0p[3] + s1p[3]);
            o.z = f22u(s0p[4] + s1p[4], s0p[5] + s1p[5]);
            o.w = f22u(s0p[6] + s1p[6], s0p[7] + s1p[7]);
            *(uint4*)&AVh[(size_t)d * QL_ + i0 + ic] = o;
        }
    }
}

// ---------------- post-LN over d_model per (b, q) ------------------------------
__global__ void __launch_bounds__(256) ln_kernel(float* __restrict__ out)
{
    const int b  = blockIdx.y;
    const int tx = threadIdx.x & 31;
    const int ty = threadIdx.x >> 5;
    const int q  = blockIdx.x * 32 + tx;
    const float* X = g_TMP + (size_t)b * DM_ * QL_;

    float s = 0.0f, s2 = 0.0f;
    for (int o = ty; o < DM_; o += 8) {
        float v = X[(size_t)o * QL_ + q];
        s += v; s2 += v * v;
    }
    __shared__ float sh[8][32], sh2[8][32];
    __shared__ float mu[32], rs[32];
    sh[ty][tx] = s; sh2[ty][tx] = s2;
    __syncthreads();
    if (ty == 0) {
        float ts = 0.0f, ts2 = 0.0f;
        #pragma unroll
        for (int k = 0; k < 8; k++) { ts += sh[k][tx]; ts2 += sh2[k][tx]; }
        float m = ts * (1.0f / DM_);
        float var = ts2 * (1.0f / DM_) - m * m;
        mu[tx] = m;
        rs[tx] = rsqrtf(var + 1e-5f);
    }
    __syncthreads();
    float m = mu[tx], r = rs[tx];
    float* O = out + (size_t)b * DM_ * QL_;
    for (int o = ty; o < DM_; o += 8)
        O[(size_t)o * QL_ + q] = (X[(size_t)o * QL_ + q] - m) * r;
}

// ---------------- launch --------------------------------------------------------
extern "C" void kernel_launch(void* const* d_in, const int* in_sizes, int n_in,
                              void* d_out, int out_size)
{
    const float* z1ss = (const float*)d_in[0];
    const float* pos  = (const float*)d_in[1];
    const float* u1ss = (const float*)d_in[2];
    const float* Wqkv = (const float*)d_in[3];
    const float* Wr   = (const float*)d_in[4];
    const float* rwb  = (const float*)d_in[5];
    const float* rrb  = (const float*)d_in[6];
    const float* Wo   = (const float*)d_in[7];
    const float* bo   = (const float*)d_in[8];
    float* out = (float*)d_out;

    cudaFuncSetAttribute(gemm_tc, cudaFuncAttributeMaxDynamicSharedMemorySize, GEMM_SMEM);
    cudaFuncSetAttribute(attn_tc, cudaFuncAttributeMaxDynamicSharedMemorySize, ATTN_SMEM);

    f2h_all<<<(F2H_N4 + 255) / 256, 256>>>(z1ss, pos, Wqkv, Wr, Wo);

    dim3 g0(QL_ / 128, 56, 1);   // fused QKV (48 y-blocks) + Wr (8 y-blocks)
    gemm_tc<<<g0, 256, GEMM_SMEM>>>(u1ss, nullptr, DM_, 3);

    dim3 ga(QL_ / 64, NH_, BSZ_);
    attn_tc<<<ga, 256, ATTN_SMEM>>>(rwb, rrb);

    dim3 g2(QL_ / 128, DM_ / 128, BSZ_);
    gemm_tc<<<g2, 256, GEMM_SMEM>>>(z1ss, bo, DM_, 2);

    dim3 g3(QL_ / 32, BSZ_);
    ln_kernel<<<g3, 256>>>(out);
}